// round 13
// baseline (speedup 1.0000x reference)
#include <cuda_runtime.h>
#include <cuda_bf16.h>
#include <math.h>

#define B_   8
#define C_   64
#define HW   65536
#define NBC  512
#define RELP 33554432

// ---------------- scratch (__device__ globals; no allocations) ----------------
__device__ float g_sum[NBC], g_sumsq[NBC];
__device__ float g_pool[NBC * 256];
__device__ float g_ap[NBC * 256];
__device__ float g_fpm[B_ * HW];
__device__ float g_hp[B_];
__device__ int   g_msbin[NBC * 256];
__device__ int   g_histms[NBC * 256];
__device__ float g_hms[NBC];
__device__ float g_na[NBC], g_meana[NBC];
__device__ int   g_pabin[B_ * 256];
__device__ int   g_histpa[B_ * 256];
__device__ float g_rowsum[B_ * 257];
__device__ float g_mi[NBC];
__device__ float g_mxv[NBC];
__device__ int   g_amx[NBC];
__device__ int   g_mink[1];
__device__ int   g_order[NBC];
__device__ float g_wsel[NBC];
__device__ float g_psum[NBC * 16], g_psumsq[NBC * 16];
__device__ float g_appart[NBC * 16 * 3 * 16];
__device__ float g_fmn[512], g_fmx[512];
__device__ int   g_histB[B_ * 256];
__device__ float g_csum[B_ * 4 * HW];   // per-(b,cg) partial channel sums (8 MB)

// ---- jax half-pixel bilinear 16->256 weights ----
__device__ __forceinline__ void up_pair(int o, int& j0, float& w0, int& j1, float& w1) {
    int i = o >> 4, r = o & 15;
    if (r < 8) {
        float f = (float)(2 * r + 17) * (1.0f / 32.0f);
        if (i == 0) { j0 = 0; w0 = 1.0f; j1 = 0; w1 = 0.0f; }
        else        { j0 = i - 1; w0 = 1.0f - f; j1 = i; w1 = f; }
    } else {
        float f = (float)(2 * r - 15) * (1.0f / 32.0f);
        if (i == 15) { j0 = 15; w0 = 1.0f; j1 = 15; w1 = 0.0f; }
        else         { j0 = i; w0 = 1.0f - f; j1 = i + 1; w1 = f; }
    }
}
__device__ __forceinline__ float up_w(int o, int j) {
    int j0, j1; float w0, w1;
    up_pair(o, j0, w0, j1, w1);
    float r = 0.0f;
    if (j == j0) r += w0;
    if (j == j1) r += w1;
    return r;
}

__device__ __forceinline__ float gfun(float c) {
    float q = c * (1.0f / 65536.0f);
    return -q * logf(fmaxf(q + 1e-8f, 1e-30f));
}
__device__ __forceinline__ int bin255(float v, float mn, float mx) {
    return (int)(__fmul_rn(__fdiv_rn(v - mn, mx - mn), 255.0f));
}
__device__ __forceinline__ float wredsum(float x) {
#pragma unroll
    for (int o = 16; o > 0; o >>= 1) x += __shfl_xor_sync(0xffffffffu, x, o);
    return x;
}

// ========== L1: bigpass (0..511) + ms binning/entropy/Gram (512..1023) ======
__global__ void bigpass_ms_kernel(const float* __restrict__ fp, const float* __restrict__ fms) {
    int blk = blockIdx.x;
    int t = threadIdx.x;
    if (blk < 512) {
        __shared__ float sv[16 * 257];
        __shared__ float sh_cs[16 * 256];
        __shared__ float xa[16 * 17];
        __shared__ float wsh[512];
        __shared__ float wy[48];
        __shared__ float sh_p[256];
        __shared__ float sh_w[16 * 8];
        int b  = blk >> 6;
        int rg = (blk >> 2) & 15;
        int cg = blk & 3;
        int px = t;

        for (int e = px; e < 512; e += 256) {
            int kx = e >> 5, q = e & 31;
            int p = 16 * kx - 8 + q;
            wsh[e] = (p >= 0 && p < 256) ? up_w(p, kx) : 0.0f;
        }
        if (px < 48) {
            int s = px >> 4, o = px & 15;
            int ky = rg - 1 + s;
            wy[px] = (ky >= 0 && ky < 16) ? up_w(rg * 16 + o, ky) : 0.0f;
        }
        if (blk < 8) g_histB[blk * 256 + px] = 0;

        float pxsum[16];
#pragma unroll
        for (int r = 0; r < 16; r++) pxsum[r] = 0.0f;

        for (int ci = 0; ci < 16; ci++) {
            int c = cg * 16 + ci;
            int bc = b * 64 + c;
            const float* base = fp + (size_t)bc * HW + rg * 4096;
            float v[16];
#pragma unroll
            for (int r = 0; r < 16; r++) v[r] = base[r * 256 + px];
            float cs = 0.0f, s2 = 0.0f;
#pragma unroll
            for (int r = 0; r < 16; r++) { cs += v[r]; s2 += v[r] * v[r]; pxsum[r] += v[r]; }
            sh_cs[ci * 256 + px] = cs;
            float wsum = wredsum(s2);
            if ((px & 31) == 0) sh_w[ci * 8 + (px >> 5)] = wsum;
#pragma unroll
            for (int r = 0; r < 16; r++) sv[r * 257 + px] = v[r];
            __syncthreads();
            {
                int o = px & 15, kx = px >> 4;
                int p0 = 16 * kx - 8;
                float acc = 0.0f;
#pragma unroll
                for (int q = 0; q < 32; q++) {
                    int p = p0 + q;
                    int pc = p < 0 ? 0 : (p > 255 ? 255 : p);
                    acc += wsh[kx * 32 + q] * sv[o * 257 + pc];
                }
                xa[kx * 17 + o] = acc;
            }
            __syncthreads();
            if (px < 48) {
                int s = px >> 4, kx = px & 15;
                int ky = rg - 1 + s;
                if (ky >= 0 && ky < 16) {
                    float acc = 0.0f;
#pragma unroll
                    for (int o = 0; o < 16; o++) acc += wy[s * 16 + o] * xa[kx * 17 + o];
                    g_appart[((bc * 16 + rg) * 3 + s) * 16 + kx] = acc;
                }
            }
        }
        __syncthreads();
        {
            int ci = px >> 4, kx = px & 15;
            float ps = 0.0f;
#pragma unroll
            for (int q = 0; q < 16; q++) ps += sh_cs[ci * 256 + kx * 16 + q];
            int bc = b * 64 + cg * 16 + ci;
            g_pool[bc * 256 + rg * 16 + kx] = ps;
            sh_p[px] = ps;
        }
        __syncthreads();
        if (px < 16) {
            float s = 0.0f;
#pragma unroll
            for (int k = 0; k < 16; k++) s += sh_p[px * 16 + k];
            g_psum[(b * 64 + cg * 16 + px) * 16 + rg] = s;
        } else if (px >= 32 && px < 48) {
            int cj = px - 32;
            float s = 0.0f;
#pragma unroll
            for (int k = 0; k < 8; k++) s += sh_w[cj * 8 + k];
            g_psumsq[(b * 64 + cg * 16 + cj) * 16 + rg] = s;
        }
#pragma unroll
        for (int r = 0; r < 16; r++)
            g_csum[(size_t)(b * 4 + cg) * HW + rg * 4096 + r * 256 + px] = pxsum[r];
    } else {
        // ---- ms binning + entropy + Gram moments (needs only fms) ----
        int bc = blk - 512;
        int lane = t & 31, wid = t >> 5;
        __shared__ float sv[256];
        __shared__ float Gsh[256], Nsh[256];
        __shared__ __align__(16) int hist[256];
        __shared__ float wr1[8], wr2[8];
        __shared__ float s_mn, s_mx;
        float v = fms[bc * 256 + t];
        sv[t] = v;
        hist[t] = 0;
        {
            int i = t >> 4, j = t & 15;
            float g = 0.0f;
            int d = i - j; if (d < 0) d = -d;
            if (d <= 1) {
                int mnij = i < j ? i : j, mxij = i < j ? j : i;
                int lo = 16 * mnij - 8; if (lo < 0) lo = 0;
                int hi = 16 * mxij + 24; if (hi > 256) hi = 256;
                for (int o = lo; o < hi; o++) g += up_w(o, i) * up_w(o, j);
            }
            Gsh[t] = g;
        }
        float mn = v, mx = v;
#pragma unroll
        for (int o = 16; o > 0; o >>= 1) {
            mn = fminf(mn, __shfl_xor_sync(0xffffffffu, mn, o));
            mx = fmaxf(mx, __shfl_xor_sync(0xffffffffu, mx, o));
        }
        if (lane == 0) { wr1[wid] = mn; wr2[wid] = mx; }
        __syncthreads();
        if (t == 0) {
            for (int q = 1; q < 8; q++) { wr1[0] = fminf(wr1[0], wr1[q]); wr2[0] = fmaxf(wr2[0], wr2[q]); }
            s_mn = wr1[0]; s_mx = wr2[0];
        }
        __syncthreads();
        int bin = bin255(v, s_mn, s_mx);
        g_msbin[bc * 256 + t] = bin;
        atomicAdd(&hist[bin], 1);
        __syncthreads();
        int h = hist[t];
        g_histms[bc * 256 + t] = h;
        float p = h * (1.0f / 256.0f);
        float ent = wredsum(-p * logf(p + 1e-8f));
        if (lane == 0) wr1[wid] = ent;
        {
            int i = t >> 4, j = t & 15;
            float n = 0.0f;
#pragma unroll
            for (int k = 0; k < 16; k++) n += sv[i * 16 + k] * Gsh[k * 16 + j];
            Nsh[t] = n;
        }
        __syncthreads();
        if (t == 0) {
            float s = 0.0f;
            for (int q = 0; q < 8; q++) s += wr1[q];
            g_hms[bc] = s;
        }
        float pp = 0.0f;
        {
            int i = t >> 4, j = t & 15;
#pragma unroll
            for (int k = 0; k < 16; k++) pp += Nsh[i * 16 + k] * sv[j * 16 + k];
        }
        float t1 = wredsum(Gsh[t] * pp);
        float t2 = wredsum(v);
        __syncthreads();
        if (lane == 0) { wr1[wid] = t1; wr2[wid] = t2; }
        __syncthreads();
        if (t == 0) {
            float SU2 = 0.0f, SM = 0.0f;
            for (int q = 0; q < 8; q++) { SU2 += wr1[q]; SM += wr2[q]; }
            float SU = 256.0f * SM;
            g_meana[bc] = SU * (1.0f / 65536.0f);
            g_na[bc] = __fsqrt_rn(SU2 - SU * SU * (1.0f / 65536.0f));
        }
    }
}

// ========== L2: reduce stats partials + assemble fpm + minmax partials ======
__global__ void mid_kernel() {
    int blk = blockIdx.x;
    int t = threadIdx.x;
    if (blk < 512) {
        int bc = blk;
        if (t == 0) {
            float s = 0.0f;
            for (int r = 0; r < 16; r++) s += g_psum[bc * 16 + r];
            g_sum[bc] = s;
        } else if (t == 32) {
            float s = 0.0f;
            for (int r = 0; r < 16; r++) s += g_psumsq[bc * 16 + r];
            g_sumsq[bc] = s;
        }
        int ky = t >> 4;
        float acc = 0.0f;
        if (ky - 1 >= 0) acc += g_appart[((bc * 16 + ky - 1) * 3 + 2) * 16 + (t & 15)];
        acc += g_appart[((bc * 16 + ky) * 3 + 1) * 16 + (t & 15)];
        if (ky + 1 < 16)  acc += g_appart[((bc * 16 + ky + 1) * 3 + 0) * 16 + (t & 15)];
        g_ap[bc * 256 + t] = acc;
    } else {
        __shared__ float ra[8], rb[8];
        int fblk = blk - 512;
        int idx4 = fblk * 256 + t;
        int b = idx4 >> 14;
        int p4 = idx4 & 16383;
        const float4* cs4 = (const float4*)g_csum;
        float4 s = cs4[(size_t)(b * 4 + 0) * 16384 + p4];
        float4 s1 = cs4[(size_t)(b * 4 + 1) * 16384 + p4];
        float4 s2 = cs4[(size_t)(b * 4 + 2) * 16384 + p4];
        float4 s3 = cs4[(size_t)(b * 4 + 3) * 16384 + p4];
        s.x = ((s.x + s1.x) + s2.x) + s3.x;
        s.y = ((s.y + s1.y) + s2.y) + s3.y;
        s.z = ((s.z + s1.z) + s2.z) + s3.z;
        s.w = ((s.w + s1.w) + s2.w) + s3.w;
        const float inv = 1.0f / 64.0f;
        s.x *= inv; s.y *= inv; s.z *= inv; s.w *= inv;
        ((float4*)g_fpm)[idx4] = s;
        float mn = fminf(fminf(s.x, s.y), fminf(s.z, s.w));
        float mx = fmaxf(fmaxf(s.x, s.y), fmaxf(s.z, s.w));
#pragma unroll
        for (int o = 16; o > 0; o >>= 1) {
            mn = fminf(mn, __shfl_xor_sync(0xffffffffu, mn, o));
            mx = fmaxf(mx, __shfl_xor_sync(0xffffffffu, mx, o));
        }
        if ((t & 31) == 0) { ra[t >> 5] = mn; rb[t >> 5] = mx; }
        __syncthreads();
        if (t == 0) {
            for (int q = 1; q < 8; q++) { mn = fminf(ra[0], ra[q]); ra[0] = mn; mx = fmaxf(rb[0], rb[q]); rb[0] = mx; }
            g_fmn[fblk] = ra[0]; g_fmx[fblk] = rb[0];
        }
    }
}

// ========== L3: histB (0..511) + smat dots/argmax (512..1023) ==========
__global__ void hist_smat_kernel(const float* __restrict__ fms) {
    int blk = blockIdx.x;
    int t = threadIdx.x;
    if (blk < 512) {
        int b = blk >> 6, chunk = blk & 63;
        __shared__ float ra[64], rb[64];
        __shared__ __align__(16) int hist[256];
        if (t < 64) { ra[t] = g_fmn[b * 64 + t]; rb[t] = g_fmx[b * 64 + t]; }
        hist[t] = 0;
        __syncthreads();
        if (t < 32) {
            float mn = fminf(ra[t], ra[t + 32]);
            float mx = fmaxf(rb[t], rb[t + 32]);
#pragma unroll
            for (int o = 16; o > 0; o >>= 1) {
                mn = fminf(mn, __shfl_xor_sync(0xffffffffu, mn, o));
                mx = fmaxf(mx, __shfl_xor_sync(0xffffffffu, mx, o));
            }
            if (t == 0) { ra[0] = mn; rb[0] = mx; }
        }
        __syncthreads();
        float mn = ra[0], mx = rb[0];
        const float* base = g_fpm + b * HW + chunk * 1024;
#pragma unroll
        for (int i = 0; i < 4; i++) {
            float v = base[i * 256 + t];
            atomicAdd(&hist[bin255(v, mn, mx)], 1);
        }
        __syncthreads();
        if (hist[t] > 0) atomicAdd(&g_histB[b * 256 + t], hist[t]);
    } else {
        // ---- similarity dots + max/argmax for one (b,c) ----
        int bc = blk - 512;
        int b = bc >> 6;
        int lane = t & 31, wid = t >> 5;
        __shared__ float sv[256];
        __shared__ float val[64];
        sv[t] = fms[bc * 256 + t];
        __syncthreads();
        float meana = g_meana[bc];
#pragma unroll
        for (int rr = 0; rr < 8; rr++) {
            int row = wid * 8 + rr;
            const float* ap = g_ap + (size_t)(b * 64 + row) * 256;
            float d = 0.0f;
#pragma unroll
            for (int q = 0; q < 8; q++) d += sv[lane + 32 * q] * ap[lane + 32 * q];
            d = wredsum(d);
            if (lane == 0) val[row] = d - meana * g_sum[b * 64 + row];
        }
        __syncthreads();
        if (t == 0) {
            float mxv = val[0]; int am = 0;
            for (int d = 1; d < 64; d++) if (val[d] > mxv) { mxv = val[d]; am = d; }
            float nb = __fsqrt_rn(g_sumsq[bc] - g_sum[bc] * g_sum[bc] * (1.0f / 65536.0f));
            float den = __fmul_rn(g_na[bc] * nb, 0.01f);
            g_mxv[bc] = __fdiv_rn(mxv, den);
            g_amx[bc] = am;
        }
    }
}

// ========== L4: parow (blocks 0..7, 512 thr) + grpsel (block 8) ==========
__global__ void parow_grpsel_kernel() {
    int t = threadIdx.x;   // 512 threads
    if (blockIdx.x < 8) {
        int b = blockIdx.x;
        __shared__ float ra[256], rb[256];
        __shared__ __align__(16) int hist[256];
        __shared__ float gts[513];
        float val = 0.0f;
        if (t < 256) {
            for (int c = 0; c < 64; c++) val += g_pool[(b * 64 + c) * 256 + t] * (1.0f / 256.0f);
            val *= (1.0f / 64.0f);
            ra[t] = val; rb[t] = val; hist[t] = 0;
        }
        for (int e = t; e < 513; e += 512) gts[e] = gfun((float)(e - 256));
        __syncthreads();
        for (int off = 128; off > 0; off >>= 1) {
            if (t < off) { ra[t] = fminf(ra[t], ra[t + off]); rb[t] = fmaxf(rb[t], rb[t + off]); }
            __syncthreads();
        }
        float mn = ra[0], mx = rb[0];
        if (t < 256) {
            int bin = bin255(val, mn, mx);
            g_pabin[b * 256 + t] = bin;
            atomicAdd(&hist[bin], 1);
        }
        __syncthreads();
        if (t < 256) {
            g_histpa[b * 256 + t] = hist[t];
            float pB = (float)g_histB[b * 256 + t] * (1.0f / 65536.0f);
            ra[t] = -pB * logf(pB + 1e-8f);
        }
        __syncthreads();
        for (int off = 128; off > 0; off >>= 1) {
            if (t < off) ra[t] += ra[t + off];
            __syncthreads();
        }
        if (t == 0) g_hp[b] = ra[0];
        if (t <= 256) {
            float acc = 0.0f;
            const int4* h4 = (const int4*)hist;
#pragma unroll 8
            for (int j4 = 0; j4 < 64; j4++) {
                int4 hh = h4[j4];
                acc += gts[512 - t - hh.x] + gts[512 - t - hh.y] + gts[512 - t - hh.z] + gts[512 - t - hh.w];
            }
            g_rowsum[b * 257 + t] = acc;
        }
    } else {
        int b = t >> 6, i = t & 63;
        __shared__ float sc[8][64], gsh[8][64], sortedv[8][64];
        __shared__ int csh[8][64];
        __shared__ int uniq[8];
        __shared__ int mk;
        sc[b][i] = g_mxv[b * 64 + i];
        gsh[b][i] = 0.0f; csh[b][i] = 0;
        __syncthreads();
        if (i == 0) {
            float mx = sc[b][0];
            for (int c = 1; c < 64; c++) mx = fmaxf(mx, sc[b][c]);
            float s = 0.0f;
            for (int c = 0; c < 64; c++) { sc[b][c] = expf(sc[b][c] - mx); s += sc[b][c]; }
            float inv = 1.0f / s;
            for (int c = 0; c < 64; c++) sc[b][c] *= inv;
        }
        __syncthreads();
        int idx = g_amx[b * 64 + i];
        atomicAdd(&gsh[b][idx], sc[b][i]);
        atomicAdd(&csh[b][idx], 1);
        __syncthreads();
        if (i == 0) {
            int u = 0;
            for (int j = 0; j < 64; j++) u += (csh[b][j] > 0) ? 1 : 0;
            uniq[b] = u;
        }
        __syncthreads();
        if (t == 0) {
            int m = uniq[0];
            for (int q = 1; q < 8; q++) m = min(m, uniq[q]);
            mk = (m + 1) >> 1;
            g_mink[0] = mk;
        }
        float vi = gsh[b][i];
        int r = 0;
        for (int j = 0; j < 64; j++) {
            float vj = gsh[b][j];
            if (vj > vi || (vj == vi && j < i)) r++;
        }
        g_order[b * 64 + r] = i;
        sortedv[b][r] = vi;
        __syncthreads();
        if (i == 0) {
            int m = mk;
            float mx = sortedv[b][0];
            float s = 0.0f;
            for (int q = 0; q < m; q++) { float e = expf(sortedv[b][q] - mx); sortedv[b][q] = e; s += e; }
            float inv = 1.0f / s;
            for (int q = 0; q < m; q++) g_wsel[b * 64 + q] = sortedv[b][q] * inv;
            for (int q = m; q < 64; q++) g_wsel[b * 64 + q] = 0.0f;
        }
    }
}

// ========== L5: final (blocks 0..511) + joint (512..1023) ==========
__global__ void joint_final_kernel(const float* __restrict__ fp, float* __restrict__ out) {
    int t = threadIdx.x;
    if (blockIdx.x < 512) {
        int blk = blockIdx.x;
        int b = blk >> 6;
        int p4 = ((blk & 63) << 8) | t;
        __shared__ int mk;
        __shared__ int ord[32];
        __shared__ float w[32];
        if (t == 0) mk = g_mink[0];
        if (t < 32) {
            ord[t] = g_order[b * 64 + t];
            w[t] = g_wsel[b * 64 + t];
        }
        __syncthreads();
        const float4* base = (const float4*)fp + (size_t)b * C_ * 16384;
        float4 m = make_float4(0.f, 0.f, 0.f, 0.f);
        int mk4 = (mk + 3) & ~3;     // w[] zero-padded, ord[] a valid permutation
        for (int r = 0; r < mk4; r += 4) {
            float4 v0 = base[(size_t)ord[r]     * 16384 + p4];
            float4 v1 = base[(size_t)ord[r + 1] * 16384 + p4];
            float4 v2 = base[(size_t)ord[r + 2] * 16384 + p4];
            float4 v3 = base[(size_t)ord[r + 3] * 16384 + p4];
            float w0 = w[r], w1 = w[r + 1], w2 = w[r + 2], w3 = w[r + 3];
            m.x += w0 / (1.0f + expf(-v0.x));
            m.y += w0 / (1.0f + expf(-v0.y));
            m.z += w0 / (1.0f + expf(-v0.z));
            m.w += w0 / (1.0f + expf(-v0.w));
            m.x += w1 / (1.0f + expf(-v1.x));
            m.y += w1 / (1.0f + expf(-v1.y));
            m.z += w1 / (1.0f + expf(-v1.z));
            m.w += w1 / (1.0f + expf(-v1.w));
            m.x += w2 / (1.0f + expf(-v2.x));
            m.y += w2 / (1.0f + expf(-v2.y));
            m.z += w2 / (1.0f + expf(-v2.z));
            m.w += w2 / (1.0f + expf(-v2.w));
            m.x += w3 / (1.0f + expf(-v3.x));
            m.y += w3 / (1.0f + expf(-v3.y));
            m.z += w3 / (1.0f + expf(-v3.z));
            m.w += w3 / (1.0f + expf(-v3.w));
        }
        float4 scl = make_float4(1.0f + m.x, 1.0f + m.y, 1.0f + m.z, 1.0f + m.w);
        float4* ob = (float4*)out + (size_t)b * C_ * 16384;
#pragma unroll 8
        for (int c = 0; c < 64; c++) {
            float4 v = base[(size_t)c * 16384 + p4];
            v.x *= scl.x; v.y *= scl.y; v.z *= scl.z; v.w *= scl.w;
            ob[(size_t)c * 16384 + p4] = v;
        }
    } else {
        int bc = blockIdx.x - 512;
        int b = bc >> 6;
        int lane = t & 31, wid = t >> 5;
        __shared__ __align__(16) int keys[256];
        __shared__ float gts[513];
        __shared__ float wr[8];
        int u = g_msbin[bc * 256 + t];
        int v = g_pabin[b * 256 + t];
        keys[t] = u * 256 + v;
        for (int e = t; e < 513; e += 256) gts[e] = gfun((float)(e - 256));
        __syncthreads();
        float acc = g_rowsum[b * 257 + g_histms[bc * 256 + t]];
        int my = keys[t], J = 0; bool first = true;
        const int4* k4 = (const int4*)keys;
#pragma unroll 4
        for (int q4 = 0; q4 < 64; q4++) {
            int4 kk = k4[q4];
            int qb = q4 << 2;
            if (kk.x == my) { J++; if (qb < t) first = false; }
            if (kk.y == my) { J++; if (qb + 1 < t) first = false; }
            if (kk.z == my) { J++; if (qb + 2 < t) first = false; }
            if (kk.w == my) { J++; if (qb + 3 < t) first = false; }
        }
        if (first) {
            int hm = g_histms[bc * 256 + u];
            int hp = g_histpa[b * 256 + v];
            int cold = 256 - hm - hp;
            acc += gts[cold + 2 * J + 256] - gts[cold + 256];
        }
        acc = wredsum(acc);
        if (lane == 0) wr[wid] = acc;
        __syncthreads();
        if (t == 0) {
            float s = 0.0f;
            for (int q = 0; q < 8; q++) s += wr[q];
            g_mi[bc] = g_hp[b] + g_hms[bc] - s;
        }
    }
}

// ========== L6: softmax(mi) + rel_ms output ==========
__global__ void relms_kernel(const float* __restrict__ fms, float* __restrict__ out) {
    int b = blockIdx.x, t = threadIdx.x;
    __shared__ float mi[64];
    if (t < 64) mi[t] = g_mi[b * 64 + t];
    __syncthreads();
    if (t == 0) {
        float mx = mi[0];
        for (int c = 1; c < 64; c++) mx = fmaxf(mx, mi[c]);
        float s = 0.0f;
        for (int c = 0; c < 64; c++) { mi[c] = expf(mi[c] - mx); s += mi[c]; }
        float inv = 1.0f / s;
        for (int c = 0; c < 64; c++) mi[c] *= inv;
    }
    __syncthreads();
    for (int c = 0; c < 64; c++) {
        int idx = (b * 64 + c) * 256 + t;
        float vv = fms[idx];
        out[RELP + idx] = vv + vv * mi[c];
    }
}

extern "C" void kernel_launch(void* const* d_in, const int* in_sizes, int n_in,
                              void* d_out, int out_size) {
    const float* fp  = (const float*)d_in[0];
    const float* fms = (const float*)d_in[1];
    if (n_in >= 2 && in_sizes[0] == B_ * C_ * 256) {
        fp  = (const float*)d_in[1];
        fms = (const float*)d_in[0];
    }
    float* out = (float*)d_out;

    bigpass_ms_kernel   <<<1024, 256>>>(fp, fms);
    mid_kernel          <<<1024, 256>>>();
    hist_smat_kernel    <<<1024, 256>>>(fms);
    parow_grpsel_kernel <<<9, 512>>>();
    joint_final_kernel  <<<1024, 256>>>(fp, out);
    relms_kernel        <<<B_, 256>>>(fms, out);
}

// round 14
// speedup vs baseline: 1.1946x; 1.1946x over previous
#include <cuda_runtime.h>
#include <cuda_bf16.h>
#include <math.h>

#define B_   8
#define C_   64
#define HW   65536
#define NBC  512
#define RELP 33554432

// ---------------- scratch (__device__ globals; no allocations) ----------------
__device__ float g_sum[NBC], g_sumsq[NBC];
__device__ float g_pool[NBC * 256];
__device__ float g_ap[NBC * 256];
__device__ float g_fpm[B_ * HW];
__device__ float g_hp[B_];
__device__ int   g_msbin[NBC * 256];
__device__ int   g_histms[NBC * 256];
__device__ float g_hms[NBC];
__device__ float g_na[NBC], g_meana[NBC];
__device__ int   g_pabin[B_ * 256];
__device__ int   g_histpa[B_ * 256];
__device__ float g_rowsum[B_ * 257];
__device__ float g_mi[NBC];
__device__ float g_mxv[NBC];
__device__ int   g_amx[NBC];
__device__ int   g_mink[1];
__device__ int   g_order[NBC];
__device__ float g_wsel[NBC];
__device__ float g_psum[NBC * 16], g_psumsq[NBC * 16];
__device__ float g_appart[NBC * 16 * 3 * 16];
__device__ float g_fmn[512], g_fmx[512];
__device__ int   g_histB[B_ * 256];
__device__ float g_csum[B_ * 4 * HW];   // per-(b,cg) partial channel sums (8 MB)

// ---- jax half-pixel bilinear 16->256 weights ----
__device__ __forceinline__ void up_pair(int o, int& j0, float& w0, int& j1, float& w1) {
    int i = o >> 4, r = o & 15;
    if (r < 8) {
        float f = (float)(2 * r + 17) * (1.0f / 32.0f);
        if (i == 0) { j0 = 0; w0 = 1.0f; j1 = 0; w1 = 0.0f; }
        else        { j0 = i - 1; w0 = 1.0f - f; j1 = i; w1 = f; }
    } else {
        float f = (float)(2 * r - 15) * (1.0f / 32.0f);
        if (i == 15) { j0 = 15; w0 = 1.0f; j1 = 15; w1 = 0.0f; }
        else         { j0 = i; w0 = 1.0f - f; j1 = i + 1; w1 = f; }
    }
}
__device__ __forceinline__ float up_w(int o, int j) {
    int j0, j1; float w0, w1;
    up_pair(o, j0, w0, j1, w1);
    float r = 0.0f;
    if (j == j0) r += w0;
    if (j == j1) r += w1;
    return r;
}

__device__ __forceinline__ float gfun(float c) {
    float q = c * (1.0f / 65536.0f);
    return -q * logf(fmaxf(q + 1e-8f, 1e-30f));
}
__device__ __forceinline__ int bin255(float v, float mn, float mx) {
    return (int)(__fmul_rn(__fdiv_rn(v - mn, mx - mn), 255.0f));
}
__device__ __forceinline__ float wredsum(float x) {
#pragma unroll
    for (int o = 16; o > 0; o >>= 1) x += __shfl_xor_sync(0xffffffffu, x, o);
    return x;
}

// ========== K1: single-read streaming pass over f_p ==========
__global__ void bigpass_kernel(const float* __restrict__ fp) {
    __shared__ float sv[16 * 257];
    __shared__ float sh_cs[16 * 256];
    __shared__ float xa[16 * 17];
    __shared__ float wsh[512];
    __shared__ float wy[48];
    __shared__ float sh_p[256];
    __shared__ float sh_w[16 * 8];
    int blk = blockIdx.x;
    int b  = blk >> 6;
    int rg = (blk >> 2) & 15;
    int cg = blk & 3;
    int px = threadIdx.x;

    for (int e = px; e < 512; e += 256) {
        int kx = e >> 5, q = e & 31;
        int p = 16 * kx - 8 + q;
        wsh[e] = (p >= 0 && p < 256) ? up_w(p, kx) : 0.0f;
    }
    if (px < 48) {
        int s = px >> 4, o = px & 15;
        int ky = rg - 1 + s;
        wy[px] = (ky >= 0 && ky < 16) ? up_w(rg * 16 + o, ky) : 0.0f;
    }
    if (blk < 8) g_histB[blk * 256 + px] = 0;

    float pxsum[16];
#pragma unroll
    for (int r = 0; r < 16; r++) pxsum[r] = 0.0f;

    for (int ci = 0; ci < 16; ci++) {
        int c = cg * 16 + ci;
        int bc = b * 64 + c;
        const float* base = fp + (size_t)bc * HW + rg * 4096;
        float v[16];
#pragma unroll
        for (int r = 0; r < 16; r++) v[r] = base[r * 256 + px];
        float cs = 0.0f, s2 = 0.0f;
#pragma unroll
        for (int r = 0; r < 16; r++) { cs += v[r]; s2 += v[r] * v[r]; pxsum[r] += v[r]; }
        sh_cs[ci * 256 + px] = cs;
        float wsum = wredsum(s2);
        if ((px & 31) == 0) sh_w[ci * 8 + (px >> 5)] = wsum;
#pragma unroll
        for (int r = 0; r < 16; r++) sv[r * 257 + px] = v[r];
        __syncthreads();
        {
            int o = px & 15, kx = px >> 4;
            int p0 = 16 * kx - 8;
            float acc = 0.0f;
#pragma unroll
            for (int q = 0; q < 32; q++) {
                int p = p0 + q;
                int pc = p < 0 ? 0 : (p > 255 ? 255 : p);
                acc += wsh[kx * 32 + q] * sv[o * 257 + pc];
            }
            xa[kx * 17 + o] = acc;
        }
        __syncthreads();
        if (px < 48) {
            int s = px >> 4, kx = px & 15;
            int ky = rg - 1 + s;
            if (ky >= 0 && ky < 16) {
                float acc = 0.0f;
#pragma unroll
                for (int o = 0; o < 16; o++) acc += wy[s * 16 + o] * xa[kx * 17 + o];
                g_appart[((bc * 16 + rg) * 3 + s) * 16 + kx] = acc;
            }
        }
    }
    __syncthreads();
    {
        int ci = px >> 4, kx = px & 15;
        float ps = 0.0f;
#pragma unroll
        for (int q = 0; q < 16; q++) ps += sh_cs[ci * 256 + kx * 16 + q];
        int bc = b * 64 + cg * 16 + ci;
        g_pool[bc * 256 + rg * 16 + kx] = ps;
        sh_p[px] = ps;
    }
    __syncthreads();
    if (px < 16) {
        float s = 0.0f;
#pragma unroll
        for (int k = 0; k < 16; k++) s += sh_p[px * 16 + k];
        g_psum[(b * 64 + cg * 16 + px) * 16 + rg] = s;
    } else if (px >= 32 && px < 48) {
        int cj = px - 32;
        float s = 0.0f;
#pragma unroll
        for (int k = 0; k < 8; k++) s += sh_w[cj * 8 + k];
        g_psumsq[(b * 64 + cg * 16 + cj) * 16 + rg] = s;
    }
#pragma unroll
    for (int r = 0; r < 16; r++)
        g_csum[(size_t)(b * 4 + cg) * HW + rg * 4096 + r * 256 + px] = pxsum[r];
}

// ========== K2: reduce stats partials + assemble fpm + minmax partials ======
__global__ void mid_kernel() {
    int blk = blockIdx.x;
    int t = threadIdx.x;
    if (blk < 512) {
        int bc = blk;
        if (t == 0) {
            float s = 0.0f;
            for (int r = 0; r < 16; r++) s += g_psum[bc * 16 + r];
            g_sum[bc] = s;
        } else if (t == 32) {
            float s = 0.0f;
            for (int r = 0; r < 16; r++) s += g_psumsq[bc * 16 + r];
            g_sumsq[bc] = s;
        }
        int ky = t >> 4;
        float acc = 0.0f;
        if (ky - 1 >= 0) acc += g_appart[((bc * 16 + ky - 1) * 3 + 2) * 16 + (t & 15)];
        acc += g_appart[((bc * 16 + ky) * 3 + 1) * 16 + (t & 15)];
        if (ky + 1 < 16)  acc += g_appart[((bc * 16 + ky + 1) * 3 + 0) * 16 + (t & 15)];
        g_ap[bc * 256 + t] = acc;
    } else {
        __shared__ float ra[8], rb[8];
        int fblk = blk - 512;
        int idx4 = fblk * 256 + t;
        int b = idx4 >> 14;
        int p4 = idx4 & 16383;
        const float4* cs4 = (const float4*)g_csum;
        float4 s = cs4[(size_t)(b * 4 + 0) * 16384 + p4];
        float4 s1 = cs4[(size_t)(b * 4 + 1) * 16384 + p4];
        float4 s2 = cs4[(size_t)(b * 4 + 2) * 16384 + p4];
        float4 s3 = cs4[(size_t)(b * 4 + 3) * 16384 + p4];
        s.x = ((s.x + s1.x) + s2.x) + s3.x;
        s.y = ((s.y + s1.y) + s2.y) + s3.y;
        s.z = ((s.z + s1.z) + s2.z) + s3.z;
        s.w = ((s.w + s1.w) + s2.w) + s3.w;
        const float inv = 1.0f / 64.0f;
        s.x *= inv; s.y *= inv; s.z *= inv; s.w *= inv;
        ((float4*)g_fpm)[idx4] = s;
        float mn = fminf(fminf(s.x, s.y), fminf(s.z, s.w));
        float mx = fmaxf(fmaxf(s.x, s.y), fmaxf(s.z, s.w));
#pragma unroll
        for (int o = 16; o > 0; o >>= 1) {
            mn = fminf(mn, __shfl_xor_sync(0xffffffffu, mn, o));
            mx = fmaxf(mx, __shfl_xor_sync(0xffffffffu, mx, o));
        }
        if ((t & 31) == 0) { ra[t >> 5] = mn; rb[t >> 5] = mx; }
        __syncthreads();
        if (t == 0) {
            for (int q = 1; q < 8; q++) { mn = fminf(ra[0], ra[q]); ra[0] = mn; mx = fmaxf(rb[0], rb[q]); rb[0] = mx; }
            g_fmn[fblk] = ra[0]; g_fmx[fblk] = rb[0];
        }
    }
}

// ========== K3: histB (blocks 0..511) + mssmat (blocks 512..1023) ==========
__global__ void hist_mssmat_kernel(const float* __restrict__ fms) {
    int blk = blockIdx.x;
    int t = threadIdx.x;
    if (blk < 512) {
        int b = blk >> 6, chunk = blk & 63;
        __shared__ float ra[64], rb[64];
        __shared__ __align__(16) int hist[256];
        if (t < 64) { ra[t] = g_fmn[b * 64 + t]; rb[t] = g_fmx[b * 64 + t]; }
        hist[t] = 0;
        __syncthreads();
        if (t < 32) {
            float mn = fminf(ra[t], ra[t + 32]);
            float mx = fmaxf(rb[t], rb[t + 32]);
#pragma unroll
            for (int o = 16; o > 0; o >>= 1) {
                mn = fminf(mn, __shfl_xor_sync(0xffffffffu, mn, o));
                mx = fmaxf(mx, __shfl_xor_sync(0xffffffffu, mx, o));
            }
            if (t == 0) { ra[0] = mn; rb[0] = mx; }
        }
        __syncthreads();
        float mn = ra[0], mx = rb[0];
        const float* base = g_fpm + b * HW + chunk * 1024;
#pragma unroll
        for (int i = 0; i < 4; i++) {
            float v = base[i * 256 + t];
            atomicAdd(&hist[bin255(v, mn, mx)], 1);
        }
        __syncthreads();
        if (hist[t] > 0) atomicAdd(&g_histB[b * 256 + t], hist[t]);
    } else {
        int bc = blk - 512;
        int b = bc >> 6;
        int lane = t & 31, wid = t >> 5;
        __shared__ float sv[256];
        __shared__ float Gsh[256], Nsh[256];
        __shared__ __align__(16) int hist[256];
        __shared__ float val[64];
        __shared__ float wr1[8], wr2[8];
        __shared__ float s_mn, s_mx, s_meana, s_na;
        float v = fms[bc * 256 + t];
        sv[t] = v;
        hist[t] = 0;
        {
            int i = t >> 4, j = t & 15;
            float g = 0.0f;
            int d = i - j; if (d < 0) d = -d;
            if (d <= 1) {
                int mnij = i < j ? i : j, mxij = i < j ? j : i;
                int lo = 16 * mnij - 8; if (lo < 0) lo = 0;
                int hi = 16 * mxij + 24; if (hi > 256) hi = 256;
                for (int o = lo; o < hi; o++) g += up_w(o, i) * up_w(o, j);
            }
            Gsh[t] = g;
        }
        float mn = v, mx = v;
#pragma unroll
        for (int o = 16; o > 0; o >>= 1) {
            mn = fminf(mn, __shfl_xor_sync(0xffffffffu, mn, o));
            mx = fmaxf(mx, __shfl_xor_sync(0xffffffffu, mx, o));
        }
        if (lane == 0) { wr1[wid] = mn; wr2[wid] = mx; }
        __syncthreads();
        if (t == 0) {
            for (int q = 1; q < 8; q++) { wr1[0] = fminf(wr1[0], wr1[q]); wr2[0] = fmaxf(wr2[0], wr2[q]); }
            s_mn = wr1[0]; s_mx = wr2[0];
        }
        __syncthreads();
        int bin = bin255(v, s_mn, s_mx);
        g_msbin[bc * 256 + t] = bin;
        atomicAdd(&hist[bin], 1);
        __syncthreads();
        int h = hist[t];
        g_histms[bc * 256 + t] = h;
        float p = h * (1.0f / 256.0f);
        float ent = wredsum(-p * logf(p + 1e-8f));
        if (lane == 0) wr1[wid] = ent;
        {
            int i = t >> 4, j = t & 15;
            float n = 0.0f;
#pragma unroll
            for (int k = 0; k < 16; k++) n += sv[i * 16 + k] * Gsh[k * 16 + j];
            Nsh[t] = n;
        }
        __syncthreads();
        if (t == 0) {
            float s = 0.0f;
            for (int q = 0; q < 8; q++) s += wr1[q];
            g_hms[bc] = s;
        }
        float pp = 0.0f;
        {
            int i = t >> 4, j = t & 15;
#pragma unroll
            for (int k = 0; k < 16; k++) pp += Nsh[i * 16 + k] * sv[j * 16 + k];
        }
        float t1 = wredsum(Gsh[t] * pp);
        float t2 = wredsum(v);
        __syncthreads();
        if (lane == 0) { wr1[wid] = t1; wr2[wid] = t2; }
        __syncthreads();
        if (t == 0) {
            float SU2 = 0.0f, SM = 0.0f;
            for (int q = 0; q < 8; q++) { SU2 += wr1[q]; SM += wr2[q]; }
            float SU = 256.0f * SM;
            s_meana = SU * (1.0f / 65536.0f);
            s_na = __fsqrt_rn(SU2 - SU * SU * (1.0f / 65536.0f));
            g_meana[bc] = s_meana;
            g_na[bc] = s_na;
        }
        __syncthreads();
        float meana = s_meana;
#pragma unroll
        for (int rr = 0; rr < 8; rr++) {
            int row = wid * 8 + rr;
            const float* ap = g_ap + (size_t)(b * 64 + row) * 256;
            float d = 0.0f;
#pragma unroll
            for (int q = 0; q < 8; q++) d += sv[lane + 32 * q] * ap[lane + 32 * q];
            d = wredsum(d);
            if (lane == 0) val[row] = d - meana * g_sum[b * 64 + row];
        }
        __syncthreads();
        if (t == 0) {
            float mxv = val[0]; int am = 0;
            for (int d = 1; d < 64; d++) if (val[d] > mxv) { mxv = val[d]; am = d; }
            float nb = __fsqrt_rn(g_sumsq[bc] - g_sum[bc] * g_sum[bc] * (1.0f / 65536.0f));
            float den = __fmul_rn(s_na * nb, 0.01f);
            g_mxv[bc] = __fdiv_rn(mxv, den);
            g_amx[bc] = am;
        }
    }
}

// ========== K4: parow (blocks 0..7, 512 thr) + grpsel (block 8) ==========
__global__ void parow_grpsel_kernel() {
    int t = threadIdx.x;   // 512 threads
    if (blockIdx.x < 8) {
        int b = blockIdx.x;
        __shared__ float ra[256], rb[256];
        __shared__ __align__(16) int hist[256];
        __shared__ float gts[513];
        float val = 0.0f;
        if (t < 256) {
            for (int c = 0; c < 64; c++) val += g_pool[(b * 64 + c) * 256 + t] * (1.0f / 256.0f);
            val *= (1.0f / 64.0f);
            ra[t] = val; rb[t] = val; hist[t] = 0;
        }
        for (int e = t; e < 513; e += 512) gts[e] = gfun((float)(e - 256));
        __syncthreads();
        for (int off = 128; off > 0; off >>= 1) {
            if (t < off) { ra[t] = fminf(ra[t], ra[t + off]); rb[t] = fmaxf(rb[t], rb[t + off]); }
            __syncthreads();
        }
        float mn = ra[0], mx = rb[0];
        if (t < 256) {
            int bin = bin255(val, mn, mx);
            g_pabin[b * 256 + t] = bin;
            atomicAdd(&hist[bin], 1);
        }
        __syncthreads();
        if (t < 256) {
            g_histpa[b * 256 + t] = hist[t];
            float pB = (float)g_histB[b * 256 + t] * (1.0f / 65536.0f);
            ra[t] = -pB * logf(pB + 1e-8f);
        }
        __syncthreads();
        for (int off = 128; off > 0; off >>= 1) {
            if (t < off) ra[t] += ra[t + off];
            __syncthreads();
        }
        if (t == 0) g_hp[b] = ra[0];
        if (t <= 256) {
            float acc = 0.0f;
            const int4* h4 = (const int4*)hist;
#pragma unroll 8
            for (int j4 = 0; j4 < 64; j4++) {
                int4 hh = h4[j4];
                acc += gts[512 - t - hh.x] + gts[512 - t - hh.y] + gts[512 - t - hh.z] + gts[512 - t - hh.w];
            }
            g_rowsum[b * 257 + t] = acc;
        }
    } else {
        int b = t >> 6, i = t & 63;
        __shared__ float sc[8][64], gsh[8][64], sortedv[8][64];
        __shared__ int csh[8][64];
        __shared__ int uniq[8];
        __shared__ int mk;
        sc[b][i] = g_mxv[b * 64 + i];
        gsh[b][i] = 0.0f; csh[b][i] = 0;
        __syncthreads();
        if (i == 0) {
            float mx = sc[b][0];
            for (int c = 1; c < 64; c++) mx = fmaxf(mx, sc[b][c]);
            float s = 0.0f;
            for (int c = 0; c < 64; c++) { sc[b][c] = expf(sc[b][c] - mx); s += sc[b][c]; }
            float inv = 1.0f / s;
            for (int c = 0; c < 64; c++) sc[b][c] *= inv;
        }
        __syncthreads();
        int idx = g_amx[b * 64 + i];
        atomicAdd(&gsh[b][idx], sc[b][i]);
        atomicAdd(&csh[b][idx], 1);
        __syncthreads();
        if (i == 0) {
            int u = 0;
            for (int j = 0; j < 64; j++) u += (csh[b][j] > 0) ? 1 : 0;
            uniq[b] = u;
        }
        __syncthreads();
        if (t == 0) {
            int m = uniq[0];
            for (int q = 1; q < 8; q++) m = min(m, uniq[q]);
            mk = (m + 1) >> 1;
            g_mink[0] = mk;
        }
        float vi = gsh[b][i];
        int r = 0;
        for (int j = 0; j < 64; j++) {
            float vj = gsh[b][j];
            if (vj > vi || (vj == vi && j < i)) r++;
        }
        g_order[b * 64 + r] = i;
        sortedv[b][r] = vi;
        __syncthreads();
        if (i == 0) {
            int m = mk;
            float mx = sortedv[b][0];
            float s = 0.0f;
            for (int q = 0; q < m; q++) { float e = expf(sortedv[b][q] - mx); sortedv[b][q] = e; s += e; }
            float inv = 1.0f / s;
            for (int q = 0; q < m; q++) g_wsel[b * 64 + q] = sortedv[b][q] * inv;
            for (int q = m; q < 64; q++) g_wsel[b * 64 + q] = 0.0f;
        }
    }
}

// ========== K5: final (blocks 0..511) + joint (blocks 512..1023) ==========
__global__ void joint_final_kernel(const float* __restrict__ fp, float* __restrict__ out) {
    int t = threadIdx.x;
    if (blockIdx.x < 512) {
        // ---- fused mask + rel_p output (float4, 4-wide mask loop) ----
        int blk = blockIdx.x;
        int b = blk >> 6;
        int p4 = ((blk & 63) << 8) | t;
        __shared__ int mk;
        __shared__ int ord[32];
        __shared__ float w[32];
        if (t == 0) mk = g_mink[0];
        if (t < 32) {
            ord[t] = g_order[b * 64 + t];
            w[t] = g_wsel[b * 64 + t];
        }
        __syncthreads();
        const float4* base = (const float4*)fp + (size_t)b * C_ * 16384;
        float4 m = make_float4(0.f, 0.f, 0.f, 0.f);
        int mk4 = (mk + 3) & ~3;   // w[] zero-padded; ord[] valid permutation
        for (int r = 0; r < mk4; r += 4) {
            float4 v0 = base[(size_t)ord[r]     * 16384 + p4];
            float4 v1 = base[(size_t)ord[r + 1] * 16384 + p4];
            float4 v2 = base[(size_t)ord[r + 2] * 16384 + p4];
            float4 v3 = base[(size_t)ord[r + 3] * 16384 + p4];
            float w0 = w[r], w1 = w[r + 1], w2 = w[r + 2], w3 = w[r + 3];
            m.x += w0 / (1.0f + expf(-v0.x));
            m.y += w0 / (1.0f + expf(-v0.y));
            m.z += w0 / (1.0f + expf(-v0.z));
            m.w += w0 / (1.0f + expf(-v0.w));
            m.x += w1 / (1.0f + expf(-v1.x));
            m.y += w1 / (1.0f + expf(-v1.y));
            m.z += w1 / (1.0f + expf(-v1.z));
            m.w += w1 / (1.0f + expf(-v1.w));
            m.x += w2 / (1.0f + expf(-v2.x));
            m.y += w2 / (1.0f + expf(-v2.y));
            m.z += w2 / (1.0f + expf(-v2.z));
            m.w += w2 / (1.0f + expf(-v2.w));
            m.x += w3 / (1.0f + expf(-v3.x));
            m.y += w3 / (1.0f + expf(-v3.y));
            m.z += w3 / (1.0f + expf(-v3.z));
            m.w += w3 / (1.0f + expf(-v3.w));
        }
        float4 scl = make_float4(1.0f + m.x, 1.0f + m.y, 1.0f + m.z, 1.0f + m.w);
        float4* ob = (float4*)out + (size_t)b * C_ * 16384;
#pragma unroll 8
        for (int c = 0; c < 64; c++) {
            float4 v = base[(size_t)c * 16384 + p4];
            v.x *= scl.x; v.y *= scl.y; v.z *= scl.z; v.w *= scl.w;
            ob[(size_t)c * 16384 + p4] = v;
        }
    } else {
        // ---- joint entropy + mi ----
        int bc = blockIdx.x - 512;
        int b = bc >> 6;
        int lane = t & 31, wid = t >> 5;
        __shared__ __align__(16) int keys[256];
        __shared__ float gts[513];
        __shared__ float wr[8];
        int u = g_msbin[bc * 256 + t];
        int v = g_pabin[b * 256 + t];
        keys[t] = u * 256 + v;
        for (int e = t; e < 513; e += 256) gts[e] = gfun((float)(e - 256));
        __syncthreads();
        float acc = g_rowsum[b * 257 + g_histms[bc * 256 + t]];
        int my = keys[t], J = 0; bool first = true;
        const int4* k4 = (const int4*)keys;
#pragma unroll 4
        for (int q4 = 0; q4 < 64; q4++) {
            int4 kk = k4[q4];
            int qb = q4 << 2;
            if (kk.x == my) { J++; if (qb < t) first = false; }
            if (kk.y == my) { J++; if (qb + 1 < t) first = false; }
            if (kk.z == my) { J++; if (qb + 2 < t) first = false; }
            if (kk.w == my) { J++; if (qb + 3 < t) first = false; }
        }
        if (first) {
            int hm = g_histms[bc * 256 + u];
            int hp = g_histpa[b * 256 + v];
            int cold = 256 - hm - hp;
            acc += gts[cold + 2 * J + 256] - gts[cold + 256];
        }
        acc = wredsum(acc);
        if (lane == 0) wr[wid] = acc;
        __syncthreads();
        if (t == 0) {
            float s = 0.0f;
            for (int q = 0; q < 8; q++) s += wr[q];
            g_mi[bc] = g_hp[b] + g_hms[bc] - s;
        }
    }
}

// ========== K6: softmax(mi) + rel_ms output ==========
__global__ void relms_kernel(const float* __restrict__ fms, float* __restrict__ out) {
    int b = blockIdx.x, t = threadIdx.x;
    __shared__ float mi[64];
    if (t < 64) mi[t] = g_mi[b * 64 + t];
    __syncthreads();
    if (t == 0) {
        float mx = mi[0];
        for (int c = 1; c < 64; c++) mx = fmaxf(mx, mi[c]);
        float s = 0.0f;
        for (int c = 0; c < 64; c++) { mi[c] = expf(mi[c] - mx); s += mi[c]; }
        float inv = 1.0f / s;
        for (int c = 0; c < 64; c++) mi[c] *= inv;
    }
    __syncthreads();
    for (int c = 0; c < 64; c++) {
        int idx = (b * 64 + c) * 256 + t;
        float vv = fms[idx];
        out[RELP + idx] = vv + vv * mi[c];
    }
}

extern "C" void kernel_launch(void* const* d_in, const int* in_sizes, int n_in,
                              void* d_out, int out_size) {
    const float* fp  = (const float*)d_in[0];
    const float* fms = (const float*)d_in[1];
    if (n_in >= 2 && in_sizes[0] == B_ * C_ * 256) {
        fp  = (const float*)d_in[1];
        fms = (const float*)d_in[0];
    }
    float* out = (float*)d_out;

    bigpass_kernel      <<<512, 256>>>(fp);
    mid_kernel          <<<1024, 256>>>();
    hist_mssmat_kernel  <<<1024, 256>>>(fms);
    parow_grpsel_kernel <<<9, 512>>>();
    joint_final_kernel  <<<1024, 256>>>(fp, out);
    relms_kernel        <<<B_, 256>>>(fms, out);
}

// round 15
// speedup vs baseline: 1.1970x; 1.0020x over previous
#include <cuda_runtime.h>
#include <cuda_bf16.h>
#include <math.h>

#define B_   8
#define C_   64
#define HW   65536
#define NBC  512
#define RELP 33554432

// ---------------- scratch (__device__ globals; no allocations) ----------------
__device__ float g_sum[NBC], g_sumsq[NBC];
__device__ float g_pool[NBC * 256];
__device__ float g_ap[NBC * 256];
__device__ float g_fpm[B_ * HW];
__device__ float g_hp[B_];
__device__ int   g_msbin[NBC * 256];
__device__ int   g_histms[NBC * 256];
__device__ float g_hms[NBC];
__device__ float g_na[NBC], g_meana[NBC];
__device__ int   g_pabin[B_ * 256];
__device__ int   g_histpa[B_ * 256];
__device__ float g_rowsum[B_ * 257];
__device__ float g_mi[NBC];
__device__ float g_mxv[NBC];
__device__ int   g_amx[NBC];
__device__ int   g_mink[1];
__device__ int   g_order[NBC];
__device__ float g_wsel[NBC];
__device__ float g_psum[NBC * 16], g_psumsq[NBC * 16];
__device__ float g_appart[NBC * 16 * 3 * 16];
__device__ float g_fmn[512], g_fmx[512];
__device__ int   g_histB[B_ * 256];
__device__ float g_csum[B_ * 4 * HW];   // per-(b,cg) partial channel sums (8 MB)

// ---- jax half-pixel bilinear 16->256 weights ----
__device__ __forceinline__ void up_pair(int o, int& j0, float& w0, int& j1, float& w1) {
    int i = o >> 4, r = o & 15;
    if (r < 8) {
        float f = (float)(2 * r + 17) * (1.0f / 32.0f);
        if (i == 0) { j0 = 0; w0 = 1.0f; j1 = 0; w1 = 0.0f; }
        else        { j0 = i - 1; w0 = 1.0f - f; j1 = i; w1 = f; }
    } else {
        float f = (float)(2 * r - 15) * (1.0f / 32.0f);
        if (i == 15) { j0 = 15; w0 = 1.0f; j1 = 15; w1 = 0.0f; }
        else         { j0 = i; w0 = 1.0f - f; j1 = i + 1; w1 = f; }
    }
}
__device__ __forceinline__ float up_w(int o, int j) {
    int j0, j1; float w0, w1;
    up_pair(o, j0, w0, j1, w1);
    float r = 0.0f;
    if (j == j0) r += w0;
    if (j == j1) r += w1;
    return r;
}

__device__ __forceinline__ float gfun(float c) {
    float q = c * (1.0f / 65536.0f);
    return -q * logf(fmaxf(q + 1e-8f, 1e-30f));
}
__device__ __forceinline__ int bin255(float v, float mn, float mx) {
    return (int)(__fmul_rn(__fdiv_rn(v - mn, mx - mn), 255.0f));
}
__device__ __forceinline__ float wredsum(float x) {
#pragma unroll
    for (int o = 16; o > 0; o >>= 1) x += __shfl_xor_sync(0xffffffffu, x, o);
    return x;
}

// ========== K1: single-read streaming pass over f_p ==========
__global__ void bigpass_kernel(const float* __restrict__ fp) {
    __shared__ float sv[16 * 257];
    __shared__ float sh_cs[16 * 256];
    __shared__ float xa[16 * 17];
    __shared__ float wsh[512];
    __shared__ float wy[48];
    __shared__ float sh_p[256];
    __shared__ float sh_w[16 * 8];
    int blk = blockIdx.x;
    int b  = blk >> 6;
    int rg = (blk >> 2) & 15;
    int cg = blk & 3;
    int px = threadIdx.x;

    for (int e = px; e < 512; e += 256) {
        int kx = e >> 5, q = e & 31;
        int p = 16 * kx - 8 + q;
        wsh[e] = (p >= 0 && p < 256) ? up_w(p, kx) : 0.0f;
    }
    if (px < 48) {
        int s = px >> 4, o = px & 15;
        int ky = rg - 1 + s;
        wy[px] = (ky >= 0 && ky < 16) ? up_w(rg * 16 + o, ky) : 0.0f;
    }
    if (blk < 8) g_histB[blk * 256 + px] = 0;

    float pxsum[16];
#pragma unroll
    for (int r = 0; r < 16; r++) pxsum[r] = 0.0f;

    for (int ci = 0; ci < 16; ci++) {
        int c = cg * 16 + ci;
        int bc = b * 64 + c;
        const float* base = fp + (size_t)bc * HW + rg * 4096;
        float v[16];
#pragma unroll
        for (int r = 0; r < 16; r++) v[r] = base[r * 256 + px];
        float cs = 0.0f, s2 = 0.0f;
#pragma unroll
        for (int r = 0; r < 16; r++) { cs += v[r]; s2 += v[r] * v[r]; pxsum[r] += v[r]; }
        sh_cs[ci * 256 + px] = cs;
        float wsum = wredsum(s2);
        if ((px & 31) == 0) sh_w[ci * 8 + (px >> 5)] = wsum;
#pragma unroll
        for (int r = 0; r < 16; r++) sv[r * 257 + px] = v[r];
        __syncthreads();
        {
            int o = px & 15, kx = px >> 4;
            int p0 = 16 * kx - 8;
            float acc = 0.0f;
#pragma unroll
            for (int q = 0; q < 32; q++) {
                int p = p0 + q;
                int pc = p < 0 ? 0 : (p > 255 ? 255 : p);
                acc += wsh[kx * 32 + q] * sv[o * 257 + pc];
            }
            xa[kx * 17 + o] = acc;
        }
        __syncthreads();
        if (px < 48) {
            int s = px >> 4, kx = px & 15;
            int ky = rg - 1 + s;
            if (ky >= 0 && ky < 16) {
                float acc = 0.0f;
#pragma unroll
                for (int o = 0; o < 16; o++) acc += wy[s * 16 + o] * xa[kx * 17 + o];
                g_appart[((bc * 16 + rg) * 3 + s) * 16 + kx] = acc;
            }
        }
    }
    __syncthreads();
    {
        int ci = px >> 4, kx = px & 15;
        float ps = 0.0f;
#pragma unroll
        for (int q = 0; q < 16; q++) ps += sh_cs[ci * 256 + kx * 16 + q];
        int bc = b * 64 + cg * 16 + ci;
        g_pool[bc * 256 + rg * 16 + kx] = ps;
        sh_p[px] = ps;
    }
    __syncthreads();
    if (px < 16) {
        float s = 0.0f;
#pragma unroll
        for (int k = 0; k < 16; k++) s += sh_p[px * 16 + k];
        g_psum[(b * 64 + cg * 16 + px) * 16 + rg] = s;
    } else if (px >= 32 && px < 48) {
        int cj = px - 32;
        float s = 0.0f;
#pragma unroll
        for (int k = 0; k < 8; k++) s += sh_w[cj * 8 + k];
        g_psumsq[(b * 64 + cg * 16 + cj) * 16 + rg] = s;
    }
#pragma unroll
    for (int r = 0; r < 16; r++)
        g_csum[(size_t)(b * 4 + cg) * HW + rg * 4096 + r * 256 + px] = pxsum[r];
}

// ========== K2: reduce stats partials + assemble fpm + minmax partials ======
__global__ void mid_kernel() {
    int blk = blockIdx.x;
    int t = threadIdx.x;
    if (blk < 512) {
        int bc = blk;
        if (t == 0) {
            float s = 0.0f;
            for (int r = 0; r < 16; r++) s += g_psum[bc * 16 + r];
            g_sum[bc] = s;
        } else if (t == 32) {
            float s = 0.0f;
            for (int r = 0; r < 16; r++) s += g_psumsq[bc * 16 + r];
            g_sumsq[bc] = s;
        }
        int ky = t >> 4;
        float acc = 0.0f;
        if (ky - 1 >= 0) acc += g_appart[((bc * 16 + ky - 1) * 3 + 2) * 16 + (t & 15)];
        acc += g_appart[((bc * 16 + ky) * 3 + 1) * 16 + (t & 15)];
        if (ky + 1 < 16)  acc += g_appart[((bc * 16 + ky + 1) * 3 + 0) * 16 + (t & 15)];
        g_ap[bc * 256 + t] = acc;
    } else {
        __shared__ float ra[8], rb[8];
        int fblk = blk - 512;
        int idx4 = fblk * 256 + t;
        int b = idx4 >> 14;
        int p4 = idx4 & 16383;
        const float4* cs4 = (const float4*)g_csum;
        float4 s = cs4[(size_t)(b * 4 + 0) * 16384 + p4];
        float4 s1 = cs4[(size_t)(b * 4 + 1) * 16384 + p4];
        float4 s2 = cs4[(size_t)(b * 4 + 2) * 16384 + p4];
        float4 s3 = cs4[(size_t)(b * 4 + 3) * 16384 + p4];
        s.x = ((s.x + s1.x) + s2.x) + s3.x;
        s.y = ((s.y + s1.y) + s2.y) + s3.y;
        s.z = ((s.z + s1.z) + s2.z) + s3.z;
        s.w = ((s.w + s1.w) + s2.w) + s3.w;
        const float inv = 1.0f / 64.0f;
        s.x *= inv; s.y *= inv; s.z *= inv; s.w *= inv;
        ((float4*)g_fpm)[idx4] = s;
        float mn = fminf(fminf(s.x, s.y), fminf(s.z, s.w));
        float mx = fmaxf(fmaxf(s.x, s.y), fmaxf(s.z, s.w));
#pragma unroll
        for (int o = 16; o > 0; o >>= 1) {
            mn = fminf(mn, __shfl_xor_sync(0xffffffffu, mn, o));
            mx = fmaxf(mx, __shfl_xor_sync(0xffffffffu, mx, o));
        }
        if ((t & 31) == 0) { ra[t >> 5] = mn; rb[t >> 5] = mx; }
        __syncthreads();
        if (t == 0) {
            for (int q = 1; q < 8; q++) { mn = fminf(ra[0], ra[q]); ra[0] = mn; mx = fmaxf(rb[0], rb[q]); rb[0] = mx; }
            g_fmn[fblk] = ra[0]; g_fmx[fblk] = rb[0];
        }
    }
}

// ========== K3: pa/rowsum (0..7) + histB (8..519) + mssmat (520..1031) ======
__global__ void pa_hist_mssmat_kernel(const float* __restrict__ fms) {
    int blk = blockIdx.x;
    int t = threadIdx.x;
    if (blk < 8) {
        // ---- pa binning + histpa + rowsum (needs only g_pool; scheduled first)
        int b = blk;
        __shared__ float ra[256], rb[256];
        __shared__ __align__(16) int hist[256];
        __shared__ float gts[513];
        float val = 0.0f;
#pragma unroll 16
        for (int c = 0; c < 64; c++) val += g_pool[(b * 64 + c) * 256 + t] * (1.0f / 256.0f);
        val *= (1.0f / 64.0f);
        for (int e = t; e < 513; e += 256) gts[e] = gfun((float)(e - 256));
        ra[t] = val; rb[t] = val; hist[t] = 0;
        __syncthreads();
        for (int off = 128; off > 0; off >>= 1) {
            if (t < off) { ra[t] = fminf(ra[t], ra[t + off]); rb[t] = fmaxf(rb[t], rb[t + off]); }
            __syncthreads();
        }
        float mn = ra[0], mx = rb[0];
        int bin = bin255(val, mn, mx);
        g_pabin[b * 256 + t] = bin;
        atomicAdd(&hist[bin], 1);
        __syncthreads();
        g_histpa[b * 256 + t] = hist[t];
        const int4* h4 = (const int4*)hist;
        for (int u = t; u <= 256; u += 256) {
            float acc = 0.0f;
#pragma unroll 8
            for (int j4 = 0; j4 < 64; j4++) {
                int4 hh = h4[j4];
                acc += gts[512 - u - hh.x] + gts[512 - u - hh.y] + gts[512 - u - hh.z] + gts[512 - u - hh.w];
            }
            g_rowsum[b * 257 + u] = acc;
        }
    } else if (blk < 520) {
        int hb = blk - 8;
        int b = hb >> 6, chunk = hb & 63;
        __shared__ float ra[64], rb[64];
        __shared__ __align__(16) int hist[256];
        if (t < 64) { ra[t] = g_fmn[b * 64 + t]; rb[t] = g_fmx[b * 64 + t]; }
        hist[t] = 0;
        __syncthreads();
        if (t < 32) {
            float mn = fminf(ra[t], ra[t + 32]);
            float mx = fmaxf(rb[t], rb[t + 32]);
#pragma unroll
            for (int o = 16; o > 0; o >>= 1) {
                mn = fminf(mn, __shfl_xor_sync(0xffffffffu, mn, o));
                mx = fmaxf(mx, __shfl_xor_sync(0xffffffffu, mx, o));
            }
            if (t == 0) { ra[0] = mn; rb[0] = mx; }
        }
        __syncthreads();
        float mn = ra[0], mx = rb[0];
        const float* base = g_fpm + b * HW + chunk * 1024;
#pragma unroll
        for (int i = 0; i < 4; i++) {
            float v = base[i * 256 + t];
            atomicAdd(&hist[bin255(v, mn, mx)], 1);
        }
        __syncthreads();
        if (hist[t] > 0) atomicAdd(&g_histB[b * 256 + t], hist[t]);
    } else {
        int bc = blk - 520;
        int b = bc >> 6;
        int lane = t & 31, wid = t >> 5;
        __shared__ float sv[256];
        __shared__ float Gsh[256], Nsh[256];
        __shared__ __align__(16) int hist[256];
        __shared__ float val[64];
        __shared__ float wr1[8], wr2[8];
        __shared__ float s_mn, s_mx, s_meana, s_na;
        float v = fms[bc * 256 + t];
        sv[t] = v;
        hist[t] = 0;
        {
            int i = t >> 4, j = t & 15;
            float g = 0.0f;
            int d = i - j; if (d < 0) d = -d;
            if (d <= 1) {
                int mnij = i < j ? i : j, mxij = i < j ? j : i;
                int lo = 16 * mnij - 8; if (lo < 0) lo = 0;
                int hi = 16 * mxij + 24; if (hi > 256) hi = 256;
                for (int o = lo; o < hi; o++) g += up_w(o, i) * up_w(o, j);
            }
            Gsh[t] = g;
        }
        float mn = v, mx = v;
#pragma unroll
        for (int o = 16; o > 0; o >>= 1) {
            mn = fminf(mn, __shfl_xor_sync(0xffffffffu, mn, o));
            mx = fmaxf(mx, __shfl_xor_sync(0xffffffffu, mx, o));
        }
        if (lane == 0) { wr1[wid] = mn; wr2[wid] = mx; }
        __syncthreads();
        if (t == 0) {
            for (int q = 1; q < 8; q++) { wr1[0] = fminf(wr1[0], wr1[q]); wr2[0] = fmaxf(wr2[0], wr2[q]); }
            s_mn = wr1[0]; s_mx = wr2[0];
        }
        __syncthreads();
        int bin = bin255(v, s_mn, s_mx);
        g_msbin[bc * 256 + t] = bin;
        atomicAdd(&hist[bin], 1);
        __syncthreads();
        int h = hist[t];
        g_histms[bc * 256 + t] = h;
        float p = h * (1.0f / 256.0f);
        float ent = wredsum(-p * logf(p + 1e-8f));
        if (lane == 0) wr1[wid] = ent;
        {
            int i = t >> 4, j = t & 15;
            float n = 0.0f;
#pragma unroll
            for (int k = 0; k < 16; k++) n += sv[i * 16 + k] * Gsh[k * 16 + j];
            Nsh[t] = n;
        }
        __syncthreads();
        if (t == 0) {
            float s = 0.0f;
            for (int q = 0; q < 8; q++) s += wr1[q];
            g_hms[bc] = s;
        }
        float pp = 0.0f;
        {
            int i = t >> 4, j = t & 15;
#pragma unroll
            for (int k = 0; k < 16; k++) pp += Nsh[i * 16 + k] * sv[j * 16 + k];
        }
        float t1 = wredsum(Gsh[t] * pp);
        float t2 = wredsum(v);
        __syncthreads();
        if (lane == 0) { wr1[wid] = t1; wr2[wid] = t2; }
        __syncthreads();
        if (t == 0) {
            float SU2 = 0.0f, SM = 0.0f;
            for (int q = 0; q < 8; q++) { SU2 += wr1[q]; SM += wr2[q]; }
            float SU = 256.0f * SM;
            s_meana = SU * (1.0f / 65536.0f);
            s_na = __fsqrt_rn(SU2 - SU * SU * (1.0f / 65536.0f));
            g_meana[bc] = s_meana;
            g_na[bc] = s_na;
        }
        __syncthreads();
        float meana = s_meana;
#pragma unroll
        for (int rr = 0; rr < 8; rr++) {
            int row = wid * 8 + rr;
            const float* ap = g_ap + (size_t)(b * 64 + row) * 256;
            float d = 0.0f;
#pragma unroll
            for (int q = 0; q < 8; q++) d += sv[lane + 32 * q] * ap[lane + 32 * q];
            d = wredsum(d);
            if (lane == 0) val[row] = d - meana * g_sum[b * 64 + row];
        }
        __syncthreads();
        if (t == 0) {
            float mxv = val[0]; int am = 0;
            for (int d = 1; d < 64; d++) if (val[d] > mxv) { mxv = val[d]; am = d; }
            float nb = __fsqrt_rn(g_sumsq[bc] - g_sum[bc] * g_sum[bc] * (1.0f / 65536.0f));
            float den = __fmul_rn(s_na * nb, 0.01f);
            g_mxv[bc] = __fdiv_rn(mxv, den);
            g_amx[bc] = am;
        }
    }
}

// ========== K4: grpsel (block 0) + hp entropy (block 1) ==========
__global__ void grpsel_hp_kernel() {
    int t = threadIdx.x;   // 512 threads
    if (blockIdx.x == 0) {
        int b = t >> 6, i = t & 63;
        __shared__ float sc[8][64], gsh[8][64], sortedv[8][64];
        __shared__ int csh[8][64];
        __shared__ int uniq[8];
        __shared__ int mk;
        sc[b][i] = g_mxv[b * 64 + i];
        gsh[b][i] = 0.0f; csh[b][i] = 0;
        __syncthreads();
        if (i == 0) {
            float mx = sc[b][0];
            for (int c = 1; c < 64; c++) mx = fmaxf(mx, sc[b][c]);
            float s = 0.0f;
            for (int c = 0; c < 64; c++) { sc[b][c] = expf(sc[b][c] - mx); s += sc[b][c]; }
            float inv = 1.0f / s;
            for (int c = 0; c < 64; c++) sc[b][c] *= inv;
        }
        __syncthreads();
        int idx = g_amx[b * 64 + i];
        atomicAdd(&gsh[b][idx], sc[b][i]);
        atomicAdd(&csh[b][idx], 1);
        __syncthreads();
        if (i == 0) {
            int u = 0;
            for (int j = 0; j < 64; j++) u += (csh[b][j] > 0) ? 1 : 0;
            uniq[b] = u;
        }
        __syncthreads();
        if (t == 0) {
            int m = uniq[0];
            for (int q = 1; q < 8; q++) m = min(m, uniq[q]);
            mk = (m + 1) >> 1;
            g_mink[0] = mk;
        }
        float vi = gsh[b][i];
        int r = 0;
        for (int j = 0; j < 64; j++) {
            float vj = gsh[b][j];
            if (vj > vi || (vj == vi && j < i)) r++;
        }
        g_order[b * 64 + r] = i;
        sortedv[b][r] = vi;
        __syncthreads();
        if (i == 0) {
            int m = mk;
            float mx = sortedv[b][0];
            float s = 0.0f;
            for (int q = 0; q < m; q++) { float e = expf(sortedv[b][q] - mx); sortedv[b][q] = e; s += e; }
            float inv = 1.0f / s;
            for (int q = 0; q < m; q++) g_wsel[b * 64 + q] = sortedv[b][q] * inv;
            for (int q = m; q < 64; q++) g_wsel[b * 64 + q] = 0.0f;
        }
    } else {
        // hp entropy for 8 batches from g_histB (continuous path)
        int b = t >> 6, i = t & 63;
        __shared__ float sh[8][64];
        float e = 0.0f;
#pragma unroll
        for (int q = 0; q < 4; q++) {
            float p = (float)g_histB[b * 256 + i * 4 + q] * (1.0f / 65536.0f);
            e += -p * logf(p + 1e-8f);
        }
        sh[b][i] = e;
        __syncthreads();
        if (i == 0) {
            float s = 0.0f;
            for (int q = 0; q < 64; q++) s += sh[b][q];
            g_hp[b] = s;
        }
    }
}

// ========== K5: final (blocks 0..511) + joint (blocks 512..1023) ==========
__global__ void joint_final_kernel(const float* __restrict__ fp, float* __restrict__ out) {
    int t = threadIdx.x;
    if (blockIdx.x < 512) {
        int blk = blockIdx.x;
        int b = blk >> 6;
        int p4 = ((blk & 63) << 8) | t;
        __shared__ int mk;
        __shared__ int ord[32];
        __shared__ float w[32];
        if (t == 0) mk = g_mink[0];
        if (t < 32) {
            ord[t] = g_order[b * 64 + t];
            w[t] = g_wsel[b * 64 + t];
        }
        __syncthreads();
        const float4* base = (const float4*)fp + (size_t)b * C_ * 16384;
        float4 m = make_float4(0.f, 0.f, 0.f, 0.f);
        int mk4 = (mk + 3) & ~3;   // w[] zero-padded; ord[] valid permutation
        for (int r = 0; r < mk4; r += 4) {
            float4 v0 = base[(size_t)ord[r]     * 16384 + p4];
            float4 v1 = base[(size_t)ord[r + 1] * 16384 + p4];
            float4 v2 = base[(size_t)ord[r + 2] * 16384 + p4];
            float4 v3 = base[(size_t)ord[r + 3] * 16384 + p4];
            float w0 = w[r], w1 = w[r + 1], w2 = w[r + 2], w3 = w[r + 3];
            m.x += w0 / (1.0f + expf(-v0.x));
            m.y += w0 / (1.0f + expf(-v0.y));
            m.z += w0 / (1.0f + expf(-v0.z));
            m.w += w0 / (1.0f + expf(-v0.w));
            m.x += w1 / (1.0f + expf(-v1.x));
            m.y += w1 / (1.0f + expf(-v1.y));
            m.z += w1 / (1.0f + expf(-v1.z));
            m.w += w1 / (1.0f + expf(-v1.w));
            m.x += w2 / (1.0f + expf(-v2.x));
            m.y += w2 / (1.0f + expf(-v2.y));
            m.z += w2 / (1.0f + expf(-v2.z));
            m.w += w2 / (1.0f + expf(-v2.w));
            m.x += w3 / (1.0f + expf(-v3.x));
            m.y += w3 / (1.0f + expf(-v3.y));
            m.z += w3 / (1.0f + expf(-v3.z));
            m.w += w3 / (1.0f + expf(-v3.w));
        }
        float4 scl = make_float4(1.0f + m.x, 1.0f + m.y, 1.0f + m.z, 1.0f + m.w);
        float4* ob = (float4*)out + (size_t)b * C_ * 16384;
#pragma unroll 8
        for (int c = 0; c < 64; c++) {
            float4 v = base[(size_t)c * 16384 + p4];
            v.x *= scl.x; v.y *= scl.y; v.z *= scl.z; v.w *= scl.w;
            ob[(size_t)c * 16384 + p4] = v;
        }
    } else {
        int bc = blockIdx.x - 512;
        int b = bc >> 6;
        int lane = t & 31, wid = t >> 5;
        __shared__ __align__(16) int keys[256];
        __shared__ float gts[513];
        __shared__ float wr[8];
        int u = g_msbin[bc * 256 + t];
        int v = g_pabin[b * 256 + t];
        keys[t] = u * 256 + v;
        for (int e = t; e < 513; e += 256) gts[e] = gfun((float)(e - 256));
        __syncthreads();
        float acc = g_rowsum[b * 257 + g_histms[bc * 256 + t]];
        int my = keys[t], J = 0; bool first = true;
        const int4* k4 = (const int4*)keys;
#pragma unroll 4
        for (int q4 = 0; q4 < 64; q4++) {
            int4 kk = k4[q4];
            int qb = q4 << 2;
            if (kk.x == my) { J++; if (qb < t) first = false; }
            if (kk.y == my) { J++; if (qb + 1 < t) first = false; }
            if (kk.z == my) { J++; if (qb + 2 < t) first = false; }
            if (kk.w == my) { J++; if (qb + 3 < t) first = false; }
        }
        if (first) {
            int hm = g_histms[bc * 256 + u];
            int hp = g_histpa[b * 256 + v];
            int cold = 256 - hm - hp;
            acc += gts[cold + 2 * J + 256] - gts[cold + 256];
        }
        acc = wredsum(acc);
        if (lane == 0) wr[wid] = acc;
        __syncthreads();
        if (t == 0) {
            float s = 0.0f;
            for (int q = 0; q < 8; q++) s += wr[q];
            g_mi[bc] = g_hp[b] + g_hms[bc] - s;
        }
    }
}

// ========== K6: softmax(mi) + rel_ms output ==========
__global__ void relms_kernel(const float* __restrict__ fms, float* __restrict__ out) {
    int b = blockIdx.x, t = threadIdx.x;
    __shared__ float mi[64];
    if (t < 64) mi[t] = g_mi[b * 64 + t];
    __syncthreads();
    if (t == 0) {
        float mx = mi[0];
        for (int c = 1; c < 64; c++) mx = fmaxf(mx, mi[c]);
        float s = 0.0f;
        for (int c = 0; c < 64; c++) { mi[c] = expf(mi[c] - mx); s += mi[c]; }
        float inv = 1.0f / s;
        for (int c = 0; c < 64; c++) mi[c] *= inv;
    }
    __syncthreads();
    for (int c = 0; c < 64; c++) {
        int idx = (b * 64 + c) * 256 + t;
        float vv = fms[idx];
        out[RELP + idx] = vv + vv * mi[c];
    }
}

extern "C" void kernel_launch(void* const* d_in, const int* in_sizes, int n_in,
                              void* d_out, int out_size) {
    const float* fp  = (const float*)d_in[0];
    const float* fms = (const float*)d_in[1];
    if (n_in >= 2 && in_sizes[0] == B_ * C_ * 256) {
        fp  = (const float*)d_in[1];
        fms = (const float*)d_in[0];
    }
    float* out = (float*)d_out;

    bigpass_kernel       <<<512, 256>>>(fp);
    mid_kernel           <<<1024, 256>>>();
    pa_hist_mssmat_kernel<<<1032, 256>>>(fms);
    grpsel_hp_kernel     <<<2, 512>>>();
    joint_final_kernel   <<<1024, 256>>>(fp, out);
    relms_kernel         <<<B_, 256>>>(fms, out);
}

// round 16
// speedup vs baseline: 1.2307x; 1.0282x over previous
#include <cuda_runtime.h>
#include <cuda_bf16.h>
#include <math.h>

#define B_   8
#define C_   64
#define HW   65536
#define NBC  512
#define RELP 33554432

#if defined(__CUDA_ARCH__) && (__CUDA_ARCH__ >= 900)
#define GRID_DEP_SYNC() cudaGridDependencySynchronize()
#else
#define GRID_DEP_SYNC() do {} while (0)
#endif

// ---------------- scratch (__device__ globals; no allocations) ----------------
__device__ float g_sum[NBC], g_sumsq[NBC];
__device__ float g_pool[NBC * 256];
__device__ float g_ap[NBC * 256];
__device__ float g_fpm[B_ * HW];
__device__ float g_hp[B_];
__device__ int   g_msbin[NBC * 256];
__device__ int   g_histms[NBC * 256];
__device__ float g_hms[NBC];
__device__ float g_na[NBC], g_meana[NBC];
__device__ int   g_pabin[B_ * 256];
__device__ int   g_histpa[B_ * 256];
__device__ float g_rowsum[B_ * 257];
__device__ float g_mi[NBC];
__device__ float g_mxv[NBC];
__device__ int   g_amx[NBC];
__device__ int   g_mink[1];
__device__ int   g_order[NBC];
__device__ float g_wsel[NBC];
__device__ float g_psum[NBC * 16], g_psumsq[NBC * 16];
__device__ float g_appart[NBC * 16 * 3 * 16];
__device__ float g_fmn[512], g_fmx[512];
__device__ int   g_histB[B_ * 256];
__device__ float g_csum[B_ * 4 * HW];

// ---- jax half-pixel bilinear 16->256 weights ----
__device__ __forceinline__ void up_pair(int o, int& j0, float& w0, int& j1, float& w1) {
    int i = o >> 4, r = o & 15;
    if (r < 8) {
        float f = (float)(2 * r + 17) * (1.0f / 32.0f);
        if (i == 0) { j0 = 0; w0 = 1.0f; j1 = 0; w1 = 0.0f; }
        else        { j0 = i - 1; w0 = 1.0f - f; j1 = i; w1 = f; }
    } else {
        float f = (float)(2 * r - 15) * (1.0f / 32.0f);
        if (i == 15) { j0 = 15; w0 = 1.0f; j1 = 15; w1 = 0.0f; }
        else         { j0 = i; w0 = 1.0f - f; j1 = i + 1; w1 = f; }
    }
}
__device__ __forceinline__ float up_w(int o, int j) {
    int j0, j1; float w0, w1;
    up_pair(o, j0, w0, j1, w1);
    float r = 0.0f;
    if (j == j0) r += w0;
    if (j == j1) r += w1;
    return r;
}

__device__ __forceinline__ float gfun(float c) {
    float q = c * (1.0f / 65536.0f);
    return -q * logf(fmaxf(q + 1e-8f, 1e-30f));
}
__device__ __forceinline__ int bin255(float v, float mn, float mx) {
    return (int)(__fmul_rn(__fdiv_rn(v - mn, mx - mn), 255.0f));
}
__device__ __forceinline__ float wredsum(float x) {
#pragma unroll
    for (int o = 16; o > 0; o >>= 1) x += __shfl_xor_sync(0xffffffffu, x, o);
    return x;
}

// ========== K1: single-read streaming pass over f_p ==========
__global__ void bigpass_kernel(const float* __restrict__ fp) {
    __shared__ float sv[16 * 257];
    __shared__ float sh_cs[16 * 256];
    __shared__ float xa[16 * 17];
    __shared__ float wsh[512];
    __shared__ float wy[48];
    __shared__ float sh_p[256];
    __shared__ float sh_w[16 * 8];
    int blk = blockIdx.x;
    int b  = blk >> 6;
    int rg = (blk >> 2) & 15;
    int cg = blk & 3;
    int px = threadIdx.x;

    for (int e = px; e < 512; e += 256) {
        int kx = e >> 5, q = e & 31;
        int p = 16 * kx - 8 + q;
        wsh[e] = (p >= 0 && p < 256) ? up_w(p, kx) : 0.0f;
    }
    if (px < 48) {
        int s = px >> 4, o = px & 15;
        int ky = rg - 1 + s;
        wy[px] = (ky >= 0 && ky < 16) ? up_w(rg * 16 + o, ky) : 0.0f;
    }
    if (blk < 8) g_histB[blk * 256 + px] = 0;

    float pxsum[16];
#pragma unroll
    for (int r = 0; r < 16; r++) pxsum[r] = 0.0f;

    for (int ci = 0; ci < 16; ci++) {
        int c = cg * 16 + ci;
        int bc = b * 64 + c;
        const float* base = fp + (size_t)bc * HW + rg * 4096;
        float v[16];
#pragma unroll
        for (int r = 0; r < 16; r++) v[r] = base[r * 256 + px];
        float cs = 0.0f, s2 = 0.0f;
#pragma unroll
        for (int r = 0; r < 16; r++) { cs += v[r]; s2 += v[r] * v[r]; pxsum[r] += v[r]; }
        sh_cs[ci * 256 + px] = cs;
        float wsum = wredsum(s2);
        if ((px & 31) == 0) sh_w[ci * 8 + (px >> 5)] = wsum;
#pragma unroll
        for (int r = 0; r < 16; r++) sv[r * 257 + px] = v[r];
        __syncthreads();
        {
            int o = px & 15, kx = px >> 4;
            int p0 = 16 * kx - 8;
            float acc = 0.0f;
#pragma unroll
            for (int q = 0; q < 32; q++) {
                int p = p0 + q;
                int pc = p < 0 ? 0 : (p > 255 ? 255 : p);
                acc += wsh[kx * 32 + q] * sv[o * 257 + pc];
            }
            xa[kx * 17 + o] = acc;
        }
        __syncthreads();
        if (px < 48) {
            int s = px >> 4, kx = px & 15;
            int ky = rg - 1 + s;
            if (ky >= 0 && ky < 16) {
                float acc = 0.0f;
#pragma unroll
                for (int o = 0; o < 16; o++) acc += wy[s * 16 + o] * xa[kx * 17 + o];
                g_appart[((bc * 16 + rg) * 3 + s) * 16 + kx] = acc;
            }
        }
    }
    __syncthreads();
    {
        int ci = px >> 4, kx = px & 15;
        float ps = 0.0f;
#pragma unroll
        for (int q = 0; q < 16; q++) ps += sh_cs[ci * 256 + kx * 16 + q];
        int bc = b * 64 + cg * 16 + ci;
        g_pool[bc * 256 + rg * 16 + kx] = ps;
        sh_p[px] = ps;
    }
    __syncthreads();
    if (px < 16) {
        float s = 0.0f;
#pragma unroll
        for (int k = 0; k < 16; k++) s += sh_p[px * 16 + k];
        g_psum[(b * 64 + cg * 16 + px) * 16 + rg] = s;
    } else if (px >= 32 && px < 48) {
        int cj = px - 32;
        float s = 0.0f;
#pragma unroll
        for (int k = 0; k < 8; k++) s += sh_w[cj * 8 + k];
        g_psumsq[(b * 64 + cg * 16 + cj) * 16 + rg] = s;
    }
#pragma unroll
    for (int r = 0; r < 16; r++)
        g_csum[(size_t)(b * 4 + cg) * HW + rg * 4096 + r * 256 + px] = pxsum[r];
}

// ========== K2: reduce stats partials + assemble fpm + minmax partials ======
__global__ void mid_kernel() {
    GRID_DEP_SYNC();
    int blk = blockIdx.x;
    int t = threadIdx.x;
    if (blk < 512) {
        int bc = blk;
        if (t == 0) {
            float s = 0.0f;
            for (int r = 0; r < 16; r++) s += g_psum[bc * 16 + r];
            g_sum[bc] = s;
        } else if (t == 32) {
            float s = 0.0f;
            for (int r = 0; r < 16; r++) s += g_psumsq[bc * 16 + r];
            g_sumsq[bc] = s;
        }
        int ky = t >> 4;
        float acc = 0.0f;
        if (ky - 1 >= 0) acc += g_appart[((bc * 16 + ky - 1) * 3 + 2) * 16 + (t & 15)];
        acc += g_appart[((bc * 16 + ky) * 3 + 1) * 16 + (t & 15)];
        if (ky + 1 < 16)  acc += g_appart[((bc * 16 + ky + 1) * 3 + 0) * 16 + (t & 15)];
        g_ap[bc * 256 + t] = acc;
    } else {
        __shared__ float ra[8], rb[8];
        int fblk = blk - 512;
        int idx4 = fblk * 256 + t;
        int b = idx4 >> 14;
        int p4 = idx4 & 16383;
        const float4* cs4 = (const float4*)g_csum;
        float4 s = cs4[(size_t)(b * 4 + 0) * 16384 + p4];
        float4 s1 = cs4[(size_t)(b * 4 + 1) * 16384 + p4];
        float4 s2 = cs4[(size_t)(b * 4 + 2) * 16384 + p4];
        float4 s3 = cs4[(size_t)(b * 4 + 3) * 16384 + p4];
        s.x = ((s.x + s1.x) + s2.x) + s3.x;
        s.y = ((s.y + s1.y) + s2.y) + s3.y;
        s.z = ((s.z + s1.z) + s2.z) + s3.z;
        s.w = ((s.w + s1.w) + s2.w) + s3.w;
        const float inv = 1.0f / 64.0f;
        s.x *= inv; s.y *= inv; s.z *= inv; s.w *= inv;
        ((float4*)g_fpm)[idx4] = s;
        float mn = fminf(fminf(s.x, s.y), fminf(s.z, s.w));
        float mx = fmaxf(fmaxf(s.x, s.y), fmaxf(s.z, s.w));
#pragma unroll
        for (int o = 16; o > 0; o >>= 1) {
            mn = fminf(mn, __shfl_xor_sync(0xffffffffu, mn, o));
            mx = fmaxf(mx, __shfl_xor_sync(0xffffffffu, mx, o));
        }
        if ((t & 31) == 0) { ra[t >> 5] = mn; rb[t >> 5] = mx; }
        __syncthreads();
        if (t == 0) {
            for (int q = 1; q < 8; q++) { mn = fminf(ra[0], ra[q]); ra[0] = mn; mx = fmaxf(rb[0], rb[q]); rb[0] = mx; }
            g_fmn[fblk] = ra[0]; g_fmx[fblk] = rb[0];
        }
    }
}

// ========== K3: pa/rowsum (0..7) + histB (8..519) + mssmat (520..1031) ======
__global__ void pa_hist_mssmat_kernel(const float* __restrict__ fms) {
    int blk = blockIdx.x;
    int t = threadIdx.x;
    if (blk < 8) {
        int b = blk;
        __shared__ float ra[256], rb[256];
        __shared__ __align__(16) int hist[256];
        __shared__ float gts[513];
        for (int e = t; e < 513; e += 256) gts[e] = gfun((float)(e - 256));
        GRID_DEP_SYNC();           // g_pool ready (bigpass, via stream order)
        float val = 0.0f;
#pragma unroll 16
        for (int c = 0; c < 64; c++) val += g_pool[(b * 64 + c) * 256 + t] * (1.0f / 256.0f);
        val *= (1.0f / 64.0f);
        ra[t] = val; rb[t] = val; hist[t] = 0;
        __syncthreads();
        for (int off = 128; off > 0; off >>= 1) {
            if (t < off) { ra[t] = fminf(ra[t], ra[t + off]); rb[t] = fmaxf(rb[t], rb[t + off]); }
            __syncthreads();
        }
        float mn = ra[0], mx = rb[0];
        int bin = bin255(val, mn, mx);
        g_pabin[b * 256 + t] = bin;
        atomicAdd(&hist[bin], 1);
        __syncthreads();
        g_histpa[b * 256 + t] = hist[t];
        const int4* h4 = (const int4*)hist;
        for (int u = t; u <= 256; u += 256) {
            float acc = 0.0f;
#pragma unroll 8
            for (int j4 = 0; j4 < 64; j4++) {
                int4 hh = h4[j4];
                acc += gts[512 - u - hh.x] + gts[512 - u - hh.y] + gts[512 - u - hh.z] + gts[512 - u - hh.w];
            }
            g_rowsum[b * 257 + u] = acc;
        }
    } else if (blk < 520) {
        GRID_DEP_SYNC();           // g_fmn/g_fmx/g_fpm ready (mid)
        int hb = blk - 8;
        int b = hb >> 6, chunk = hb & 63;
        __shared__ float ra[64], rb[64];
        __shared__ __align__(16) int hist[256];
        if (t < 64) { ra[t] = g_fmn[b * 64 + t]; rb[t] = g_fmx[b * 64 + t]; }
        hist[t] = 0;
        __syncthreads();
        if (t < 32) {
            float mn = fminf(ra[t], ra[t + 32]);
            float mx = fmaxf(rb[t], rb[t + 32]);
#pragma unroll
            for (int o = 16; o > 0; o >>= 1) {
                mn = fminf(mn, __shfl_xor_sync(0xffffffffu, mn, o));
                mx = fmaxf(mx, __shfl_xor_sync(0xffffffffu, mx, o));
            }
            if (t == 0) { ra[0] = mn; rb[0] = mx; }
        }
        __syncthreads();
        float mn = ra[0], mx = rb[0];
        const float* base = g_fpm + b * HW + chunk * 1024;
#pragma unroll
        for (int i = 0; i < 4; i++) {
            float v = base[i * 256 + t];
            atomicAdd(&hist[bin255(v, mn, mx)], 1);
        }
        __syncthreads();
        if (hist[t] > 0) atomicAdd(&g_histB[b * 256 + t], hist[t]);
    } else {
        // ---- ms part (fms-only): fully overlapped with upstream ----
        int bc = blk - 520;
        int b = bc >> 6;
        int lane = t & 31, wid = t >> 5;
        __shared__ float sv[256];
        __shared__ float Gsh[256], Nsh[256];
        __shared__ __align__(16) int hist[256];
        __shared__ float val[64];
        __shared__ float wr1[8], wr2[8];
        __shared__ float s_mn, s_mx, s_meana, s_na;
        float v = fms[bc * 256 + t];
        sv[t] = v;
        hist[t] = 0;
        {
            int i = t >> 4, j = t & 15;
            float g = 0.0f;
            int d = i - j; if (d < 0) d = -d;
            if (d <= 1) {
                int mnij = i < j ? i : j, mxij = i < j ? j : i;
                int lo = 16 * mnij - 8; if (lo < 0) lo = 0;
                int hi = 16 * mxij + 24; if (hi > 256) hi = 256;
                for (int o = lo; o < hi; o++) g += up_w(o, i) * up_w(o, j);
            }
            Gsh[t] = g;
        }
        float mn = v, mx = v;
#pragma unroll
        for (int o = 16; o > 0; o >>= 1) {
            mn = fminf(mn, __shfl_xor_sync(0xffffffffu, mn, o));
            mx = fmaxf(mx, __shfl_xor_sync(0xffffffffu, mx, o));
        }
        if (lane == 0) { wr1[wid] = mn; wr2[wid] = mx; }
        __syncthreads();
        if (t == 0) {
            for (int q = 1; q < 8; q++) { wr1[0] = fminf(wr1[0], wr1[q]); wr2[0] = fmaxf(wr2[0], wr2[q]); }
            s_mn = wr1[0]; s_mx = wr2[0];
        }
        __syncthreads();
        int bin = bin255(v, s_mn, s_mx);
        g_msbin[bc * 256 + t] = bin;
        atomicAdd(&hist[bin], 1);
        __syncthreads();
        int h = hist[t];
        g_histms[bc * 256 + t] = h;
        float p = h * (1.0f / 256.0f);
        float ent = wredsum(-p * logf(p + 1e-8f));
        if (lane == 0) wr1[wid] = ent;
        {
            int i = t >> 4, j = t & 15;
            float n = 0.0f;
#pragma unroll
            for (int k = 0; k < 16; k++) n += sv[i * 16 + k] * Gsh[k * 16 + j];
            Nsh[t] = n;
        }
        __syncthreads();
        if (t == 0) {
            float s = 0.0f;
            for (int q = 0; q < 8; q++) s += wr1[q];
            g_hms[bc] = s;
        }
        float pp = 0.0f;
        {
            int i = t >> 4, j = t & 15;
#pragma unroll
            for (int k = 0; k < 16; k++) pp += Nsh[i * 16 + k] * sv[j * 16 + k];
        }
        float t1 = wredsum(Gsh[t] * pp);
        float t2 = wredsum(v);
        __syncthreads();
        if (lane == 0) { wr1[wid] = t1; wr2[wid] = t2; }
        __syncthreads();
        if (t == 0) {
            float SU2 = 0.0f, SM = 0.0f;
            for (int q = 0; q < 8; q++) { SU2 += wr1[q]; SM += wr2[q]; }
            float SU = 256.0f * SM;
            s_meana = SU * (1.0f / 65536.0f);
            s_na = __fsqrt_rn(SU2 - SU * SU * (1.0f / 65536.0f));
            g_meana[bc] = s_meana;
            g_na[bc] = s_na;
        }
        __syncthreads();
        // ---- smat part: needs g_ap/g_sum/g_sumsq from mid ----
        GRID_DEP_SYNC();
        float meana = s_meana;
#pragma unroll
        for (int rr = 0; rr < 8; rr++) {
            int row = wid * 8 + rr;
            const float* ap = g_ap + (size_t)(b * 64 + row) * 256;
            float d = 0.0f;
#pragma unroll
            for (int q = 0; q < 8; q++) d += sv[lane + 32 * q] * ap[lane + 32 * q];
            d = wredsum(d);
            if (lane == 0) val[row] = d - meana * g_sum[b * 64 + row];
        }
        __syncthreads();
        if (t == 0) {
            float mxv = val[0]; int am = 0;
            for (int d = 1; d < 64; d++) if (val[d] > mxv) { mxv = val[d]; am = d; }
            float nb = __fsqrt_rn(g_sumsq[bc] - g_sum[bc] * g_sum[bc] * (1.0f / 65536.0f));
            float den = __fmul_rn(s_na * nb, 0.01f);
            g_mxv[bc] = __fdiv_rn(mxv, den);
            g_amx[bc] = am;
        }
    }
}

// ========== K4: grpsel (block 0) + hp entropy (block 1) ==========
__global__ void grpsel_hp_kernel() {
    GRID_DEP_SYNC();
    int t = threadIdx.x;
    if (blockIdx.x == 0) {
        int b = t >> 6, i = t & 63;
        __shared__ float sc[8][64], gsh[8][64], sortedv[8][64];
        __shared__ int csh[8][64];
        __shared__ int uniq[8];
        __shared__ int mk;
        sc[b][i] = g_mxv[b * 64 + i];
        gsh[b][i] = 0.0f; csh[b][i] = 0;
        __syncthreads();
        if (i == 0) {
            float mx = sc[b][0];
            for (int c = 1; c < 64; c++) mx = fmaxf(mx, sc[b][c]);
            float s = 0.0f;
            for (int c = 0; c < 64; c++) { sc[b][c] = expf(sc[b][c] - mx); s += sc[b][c]; }
            float inv = 1.0f / s;
            for (int c = 0; c < 64; c++) sc[b][c] *= inv;
        }
        __syncthreads();
        int idx = g_amx[b * 64 + i];
        atomicAdd(&gsh[b][idx], sc[b][i]);
        atomicAdd(&csh[b][idx], 1);
        __syncthreads();
        if (i == 0) {
            int u = 0;
            for (int j = 0; j < 64; j++) u += (csh[b][j] > 0) ? 1 : 0;
            uniq[b] = u;
        }
        __syncthreads();
        if (t == 0) {
            int m = uniq[0];
            for (int q = 1; q < 8; q++) m = min(m, uniq[q]);
            mk = (m + 1) >> 1;
            g_mink[0] = mk;
        }
        float vi = gsh[b][i];
        int r = 0;
        for (int j = 0; j < 64; j++) {
            float vj = gsh[b][j];
            if (vj > vi || (vj == vi && j < i)) r++;
        }
        g_order[b * 64 + r] = i;
        sortedv[b][r] = vi;
        __syncthreads();
        if (i == 0) {
            int m = mk;
            float mx = sortedv[b][0];
            float s = 0.0f;
            for (int q = 0; q < m; q++) { float e = expf(sortedv[b][q] - mx); sortedv[b][q] = e; s += e; }
            float inv = 1.0f / s;
            for (int q = 0; q < m; q++) g_wsel[b * 64 + q] = sortedv[b][q] * inv;
            for (int q = m; q < 64; q++) g_wsel[b * 64 + q] = 0.0f;
        }
    } else {
        int b = t >> 6, i = t & 63;
        __shared__ float sh[8][64];
        float e = 0.0f;
#pragma unroll
        for (int q = 0; q < 4; q++) {
            float p = (float)g_histB[b * 256 + i * 4 + q] * (1.0f / 65536.0f);
            e += -p * logf(p + 1e-8f);
        }
        sh[b][i] = e;
        __syncthreads();
        if (i == 0) {
            float s = 0.0f;
            for (int q = 0; q < 64; q++) s += sh[b][q];
            g_hp[b] = s;
        }
    }
}

// ========== K5: final (blocks 0..511) + joint (blocks 512..1023) ==========
__global__ void joint_final_kernel(const float* __restrict__ fp, float* __restrict__ out) {
    int t = threadIdx.x;
    if (blockIdx.x < 512) {
        GRID_DEP_SYNC();
        int blk = blockIdx.x;
        int b = blk >> 6;
        int p4 = ((blk & 63) << 8) | t;
        __shared__ int mk;
        __shared__ int ord[32];
        __shared__ float w[32];
        if (t == 0) mk = g_mink[0];
        if (t < 32) {
            ord[t] = g_order[b * 64 + t];
            w[t] = g_wsel[b * 64 + t];
        }
        __syncthreads();
        const float4* base = (const float4*)fp + (size_t)b * C_ * 16384;
        float4 m = make_float4(0.f, 0.f, 0.f, 0.f);
        int mk4 = (mk + 3) & ~3;
        for (int r = 0; r < mk4; r += 4) {
            float4 v0 = base[(size_t)ord[r]     * 16384 + p4];
            float4 v1 = base[(size_t)ord[r + 1] * 16384 + p4];
            float4 v2 = base[(size_t)ord[r + 2] * 16384 + p4];
            float4 v3 = base[(size_t)ord[r + 3] * 16384 + p4];
            float w0 = w[r], w1 = w[r + 1], w2 = w[r + 2], w3 = w[r + 3];
            m.x += w0 / (1.0f + expf(-v0.x));
            m.y += w0 / (1.0f + expf(-v0.y));
            m.z += w0 / (1.0f + expf(-v0.z));
            m.w += w0 / (1.0f + expf(-v0.w));
            m.x += w1 / (1.0f + expf(-v1.x));
            m.y += w1 / (1.0f + expf(-v1.y));
            m.z += w1 / (1.0f + expf(-v1.z));
            m.w += w1 / (1.0f + expf(-v1.w));
            m.x += w2 / (1.0f + expf(-v2.x));
            m.y += w2 / (1.0f + expf(-v2.y));
            m.z += w2 / (1.0f + expf(-v2.z));
            m.w += w2 / (1.0f + expf(-v2.w));
            m.x += w3 / (1.0f + expf(-v3.x));
            m.y += w3 / (1.0f + expf(-v3.y));
            m.z += w3 / (1.0f + expf(-v3.z));
            m.w += w3 / (1.0f + expf(-v3.w));
        }
        float4 scl = make_float4(1.0f + m.x, 1.0f + m.y, 1.0f + m.z, 1.0f + m.w);
        float4* ob = (float4*)out + (size_t)b * C_ * 16384;
#pragma unroll 8
        for (int c = 0; c < 64; c++) {
            float4 v = base[(size_t)c * 16384 + p4];
            v.x *= scl.x; v.y *= scl.y; v.z *= scl.z; v.w *= scl.w;
            ob[(size_t)c * 16384 + p4] = v;
        }
    } else {
        int bc = blockIdx.x - 512;
        int b = bc >> 6;
        int lane = t & 31, wid = t >> 5;
        __shared__ __align__(16) int keys[256];
        __shared__ float gts[513];
        __shared__ float wr[8];
        for (int e = t; e < 513; e += 256) gts[e] = gfun((float)(e - 256));
        GRID_DEP_SYNC();
        int u = g_msbin[bc * 256 + t];
        int v = g_pabin[b * 256 + t];
        keys[t] = u * 256 + v;
        __syncthreads();
        float acc = g_rowsum[b * 257 + g_histms[bc * 256 + t]];
        int my = keys[t], J = 0; bool first = true;
        const int4* k4 = (const int4*)keys;
#pragma unroll 4
        for (int q4 = 0; q4 < 64; q4++) {
            int4 kk = k4[q4];
            int qb = q4 << 2;
            if (kk.x == my) { J++; if (qb < t) first = false; }
            if (kk.y == my) { J++; if (qb + 1 < t) first = false; }
            if (kk.z == my) { J++; if (qb + 2 < t) first = false; }
            if (kk.w == my) { J++; if (qb + 3 < t) first = false; }
        }
        if (first) {
            int hm = g_histms[bc * 256 + u];
            int hp = g_histpa[b * 256 + v];
            int cold = 256 - hm - hp;
            acc += gts[cold + 2 * J + 256] - gts[cold + 256];
        }
        acc = wredsum(acc);
        if (lane == 0) wr[wid] = acc;
        __syncthreads();
        if (t == 0) {
            float s = 0.0f;
            for (int q = 0; q < 8; q++) s += wr[q];
            g_mi[bc] = g_hp[b] + g_hms[bc] - s;
        }
    }
}

// ========== K6: softmax(mi) + rel_ms output ==========
__global__ void relms_kernel(const float* __restrict__ fms, float* __restrict__ out) {
    GRID_DEP_SYNC();
    int b = blockIdx.x, t = threadIdx.x;
    __shared__ float mi[64];
    if (t < 64) mi[t] = g_mi[b * 64 + t];
    __syncthreads();
    if (t == 0) {
        float mx = mi[0];
        for (int c = 1; c < 64; c++) mx = fmaxf(mx, mi[c]);
        float s = 0.0f;
        for (int c = 0; c < 64; c++) { mi[c] = expf(mi[c] - mx); s += mi[c]; }
        float inv = 1.0f / s;
        for (int c = 0; c < 64; c++) mi[c] *= inv;
    }
    __syncthreads();
    for (int c = 0; c < 64; c++) {
        int idx = (b * 64 + c) * 256 + t;
        float vv = fms[idx];
        out[RELP + idx] = vv + vv * mi[c];
    }
}

// ---------------- host: PDL launches with plain fallback ----------------
template <typename K, typename... Args>
static inline void launch_pdl(K kernel, dim3 grid, dim3 block, bool pdl, Args... args) {
    cudaLaunchConfig_t cfg = {};
    cfg.gridDim = grid;
    cfg.blockDim = block;
    cfg.dynamicSmemBytes = 0;
    cfg.stream = 0;
    cudaLaunchAttribute attr[1];
    if (pdl) {
        attr[0].id = cudaLaunchAttributeProgrammaticStreamSerialization;
        attr[0].val.programmaticStreamSerializationAllowed = 1;
        cfg.attrs = attr;
        cfg.numAttrs = 1;
    }
    cudaError_t err = cudaLaunchKernelEx(&cfg, kernel, args...);
    if (err != cudaSuccess) {
        (void)cudaGetLastError();           // clear
        cfg.attrs = nullptr; cfg.numAttrs = 0;
        cudaLaunchKernelEx(&cfg, kernel, args...);
    }
}

extern "C" void kernel_launch(void* const* d_in, const int* in_sizes, int n_in,
                              void* d_out, int out_size) {
    const float* fp  = (const float*)d_in[0];
    const float* fms = (const float*)d_in[1];
    if (n_in >= 2 && in_sizes[0] == B_ * C_ * 256) {
        fp  = (const float*)d_in[1];
        fms = (const float*)d_in[0];
    }
    float* out = (float*)d_out;

    launch_pdl(bigpass_kernel,        dim3(512),  dim3(256), false, fp);
    launch_pdl(mid_kernel,            dim3(1024), dim3(256), true);
    launch_pdl(pa_hist_mssmat_kernel, dim3(1032), dim3(256), true,  fms);
    launch_pdl(grpsel_hp_kernel,      dim3(2),    dim3(512), true);
    launch_pdl(joint_final_kernel,    dim3(1024), dim3(256), true,  fp, out);
    launch_pdl(relms_kernel,          dim3(B_),   dim3(256), true,  fms, out);
}

// round 17
// speedup vs baseline: 1.2493x; 1.0151x over previous
#include <cuda_runtime.h>
#include <cuda_bf16.h>
#include <math.h>

#define B_   8
#define C_   64
#define HW   65536
#define NBC  512
#define RELP 33554432

#if defined(__CUDA_ARCH__) && (__CUDA_ARCH__ >= 900)
#define GRID_DEP_SYNC() cudaGridDependencySynchronize()
#else
#define GRID_DEP_SYNC() do {} while (0)
#endif

// ---------------- scratch (__device__ globals; no allocations) ----------------
__device__ float g_sum[NBC], g_sumsq[NBC];
__device__ float g_pool[NBC * 256];
__device__ float g_ap[NBC * 256];
__device__ float g_fpm[B_ * HW];
__device__ float g_hp[B_];
__device__ int   g_msbin[NBC * 256];
__device__ int   g_histms[NBC * 256];
__device__ float g_hms[NBC];
__device__ float g_na[NBC], g_meana[NBC];
__device__ int   g_pabin[B_ * 256];
__device__ int   g_histpa[B_ * 256];
__device__ float g_rowsum[B_ * 257];
__device__ float g_mi[NBC];
__device__ float g_mxv[NBC];
__device__ int   g_amx[NBC];
__device__ float g_psum[NBC * 16], g_psumsq[NBC * 16];
__device__ float g_appart[NBC * 16 * 3 * 16];
__device__ float g_fmn[512], g_fmx[512];
__device__ int   g_histB[B_ * 256];
__device__ int   g_cnt_hist;
__device__ float g_csum[B_ * 4 * HW];

// ---- jax half-pixel bilinear 16->256 weights ----
__device__ __forceinline__ void up_pair(int o, int& j0, float& w0, int& j1, float& w1) {
    int i = o >> 4, r = o & 15;
    if (r < 8) {
        float f = (float)(2 * r + 17) * (1.0f / 32.0f);
        if (i == 0) { j0 = 0; w0 = 1.0f; j1 = 0; w1 = 0.0f; }
        else        { j0 = i - 1; w0 = 1.0f - f; j1 = i; w1 = f; }
    } else {
        float f = (float)(2 * r - 15) * (1.0f / 32.0f);
        if (i == 15) { j0 = 15; w0 = 1.0f; j1 = 15; w1 = 0.0f; }
        else         { j0 = i; w0 = 1.0f - f; j1 = i + 1; w1 = f; }
    }
}
__device__ __forceinline__ float up_w(int o, int j) {
    int j0, j1; float w0, w1;
    up_pair(o, j0, w0, j1, w1);
    float r = 0.0f;
    if (j == j0) r += w0;
    if (j == j1) r += w1;
    return r;
}

__device__ __forceinline__ float gfun(float c) {
    float q = c * (1.0f / 65536.0f);
    return -q * logf(fmaxf(q + 1e-8f, 1e-30f));
}
__device__ __forceinline__ int bin255(float v, float mn, float mx) {
    return (int)(__fmul_rn(__fdiv_rn(v - mn, mx - mn), 255.0f));
}
__device__ __forceinline__ float wredsum(float x) {
#pragma unroll
    for (int o = 16; o > 0; o >>= 1) x += __shfl_xor_sync(0xffffffffu, x, o);
    return x;
}

// ========== K1: single-read streaming pass over f_p ==========
__global__ void bigpass_kernel(const float* __restrict__ fp) {
    __shared__ float sv[16 * 257];
    __shared__ float sh_cs[16 * 256];
    __shared__ float xa[16 * 17];
    __shared__ float wsh[512];
    __shared__ float wy[48];
    __shared__ float sh_p[256];
    __shared__ float sh_w[16 * 8];
    int blk = blockIdx.x;
    int b  = blk >> 6;
    int rg = (blk >> 2) & 15;
    int cg = blk & 3;
    int px = threadIdx.x;

    for (int e = px; e < 512; e += 256) {
        int kx = e >> 5, q = e & 31;
        int p = 16 * kx - 8 + q;
        wsh[e] = (p >= 0 && p < 256) ? up_w(p, kx) : 0.0f;
    }
    if (px < 48) {
        int s = px >> 4, o = px & 15;
        int ky = rg - 1 + s;
        wy[px] = (ky >= 0 && ky < 16) ? up_w(rg * 16 + o, ky) : 0.0f;
    }
    if (blk < 8) g_histB[blk * 256 + px] = 0;
    if (blk == 0 && px == 0) g_cnt_hist = 0;

    float pxsum[16];
#pragma unroll
    for (int r = 0; r < 16; r++) pxsum[r] = 0.0f;

    for (int ci = 0; ci < 16; ci++) {
        int c = cg * 16 + ci;
        int bc = b * 64 + c;
        const float* base = fp + (size_t)bc * HW + rg * 4096;
        float v[16];
#pragma unroll
        for (int r = 0; r < 16; r++) v[r] = base[r * 256 + px];
        float cs = 0.0f, s2 = 0.0f;
#pragma unroll
        for (int r = 0; r < 16; r++) { cs += v[r]; s2 += v[r] * v[r]; pxsum[r] += v[r]; }
        sh_cs[ci * 256 + px] = cs;
        float wsum = wredsum(s2);
        if ((px & 31) == 0) sh_w[ci * 8 + (px >> 5)] = wsum;
#pragma unroll
        for (int r = 0; r < 16; r++) sv[r * 257 + px] = v[r];
        __syncthreads();
        {
            int o = px & 15, kx = px >> 4;
            int p0 = 16 * kx - 8;
            float acc = 0.0f;
#pragma unroll
            for (int q = 0; q < 32; q++) {
                int p = p0 + q;
                int pc = p < 0 ? 0 : (p > 255 ? 255 : p);
                acc += wsh[kx * 32 + q] * sv[o * 257 + pc];
            }
            xa[kx * 17 + o] = acc;
        }
        __syncthreads();
        if (px < 48) {
            int s = px >> 4, kx = px & 15;
            int ky = rg - 1 + s;
            if (ky >= 0 && ky < 16) {
                float acc = 0.0f;
#pragma unroll
                for (int o = 0; o < 16; o++) acc += wy[s * 16 + o] * xa[kx * 17 + o];
                g_appart[((bc * 16 + rg) * 3 + s) * 16 + kx] = acc;
            }
        }
    }
    __syncthreads();
    {
        int ci = px >> 4, kx = px & 15;
        float ps = 0.0f;
#pragma unroll
        for (int q = 0; q < 16; q++) ps += sh_cs[ci * 256 + kx * 16 + q];
        int bc = b * 64 + cg * 16 + ci;
        g_pool[bc * 256 + rg * 16 + kx] = ps;
        sh_p[px] = ps;
    }
    __syncthreads();
    if (px < 16) {
        float s = 0.0f;
#pragma unroll
        for (int k = 0; k < 16; k++) s += sh_p[px * 16 + k];
        g_psum[(b * 64 + cg * 16 + px) * 16 + rg] = s;
    } else if (px >= 32 && px < 48) {
        int cj = px - 32;
        float s = 0.0f;
#pragma unroll
        for (int k = 0; k < 8; k++) s += sh_w[cj * 8 + k];
        g_psumsq[(b * 64 + cg * 16 + cj) * 16 + rg] = s;
    }
#pragma unroll
    for (int r = 0; r < 16; r++)
        g_csum[(size_t)(b * 4 + cg) * HW + rg * 4096 + r * 256 + px] = pxsum[r];
}

// ========== K2: reduce stats partials + assemble fpm + minmax partials ======
__global__ void mid_kernel() {
    GRID_DEP_SYNC();
    int blk = blockIdx.x;
    int t = threadIdx.x;
    if (blk < 512) {
        int bc = blk;
        if (t == 0) {
            float s = 0.0f;
            for (int r = 0; r < 16; r++) s += g_psum[bc * 16 + r];
            g_sum[bc] = s;
        } else if (t == 32) {
            float s = 0.0f;
            for (int r = 0; r < 16; r++) s += g_psumsq[bc * 16 + r];
            g_sumsq[bc] = s;
        }
        int ky = t >> 4;
        float acc = 0.0f;
        if (ky - 1 >= 0) acc += g_appart[((bc * 16 + ky - 1) * 3 + 2) * 16 + (t & 15)];
        acc += g_appart[((bc * 16 + ky) * 3 + 1) * 16 + (t & 15)];
        if (ky + 1 < 16)  acc += g_appart[((bc * 16 + ky + 1) * 3 + 0) * 16 + (t & 15)];
        g_ap[bc * 256 + t] = acc;
    } else {
        __shared__ float ra[8], rb[8];
        int fblk = blk - 512;
        int idx4 = fblk * 256 + t;
        int b = idx4 >> 14;
        int p4 = idx4 & 16383;
        const float4* cs4 = (const float4*)g_csum;
        float4 s = cs4[(size_t)(b * 4 + 0) * 16384 + p4];
        float4 s1 = cs4[(size_t)(b * 4 + 1) * 16384 + p4];
        float4 s2 = cs4[(size_t)(b * 4 + 2) * 16384 + p4];
        float4 s3 = cs4[(size_t)(b * 4 + 3) * 16384 + p4];
        s.x = ((s.x + s1.x) + s2.x) + s3.x;
        s.y = ((s.y + s1.y) + s2.y) + s3.y;
        s.z = ((s.z + s1.z) + s2.z) + s3.z;
        s.w = ((s.w + s1.w) + s2.w) + s3.w;
        const float inv = 1.0f / 64.0f;
        s.x *= inv; s.y *= inv; s.z *= inv; s.w *= inv;
        ((float4*)g_fpm)[idx4] = s;
        float mn = fminf(fminf(s.x, s.y), fminf(s.z, s.w));
        float mx = fmaxf(fmaxf(s.x, s.y), fmaxf(s.z, s.w));
#pragma unroll
        for (int o = 16; o > 0; o >>= 1) {
            mn = fminf(mn, __shfl_xor_sync(0xffffffffu, mn, o));
            mx = fmaxf(mx, __shfl_xor_sync(0xffffffffu, mx, o));
        }
        if ((t & 31) == 0) { ra[t >> 5] = mn; rb[t >> 5] = mx; }
        __syncthreads();
        if (t == 0) {
            for (int q = 1; q < 8; q++) { mn = fminf(ra[0], ra[q]); ra[0] = mn; mx = fmaxf(rb[0], rb[q]); rb[0] = mx; }
            g_fmn[fblk] = ra[0]; g_fmx[fblk] = rb[0];
        }
    }
}

// ========== K3: pa/rowsum (0..7) + histB+hp (8..519) + mssmat (520..1031) ====
__global__ void pa_hist_mssmat_kernel(const float* __restrict__ fms) {
    int blk = blockIdx.x;
    int t = threadIdx.x;
    if (blk < 8) {
        int b = blk;
        __shared__ float ra[256], rb[256];
        __shared__ __align__(16) int hist[256];
        __shared__ float gts[513];
        for (int e = t; e < 513; e += 256) gts[e] = gfun((float)(e - 256));
        GRID_DEP_SYNC();           // g_pool ready (bigpass, via stream order)
        float val = 0.0f;
#pragma unroll 16
        for (int c = 0; c < 64; c++) val += g_pool[(b * 64 + c) * 256 + t] * (1.0f / 256.0f);
        val *= (1.0f / 64.0f);
        ra[t] = val; rb[t] = val; hist[t] = 0;
        __syncthreads();
        for (int off = 128; off > 0; off >>= 1) {
            if (t < off) { ra[t] = fminf(ra[t], ra[t + off]); rb[t] = fmaxf(rb[t], rb[t + off]); }
            __syncthreads();
        }
        float mn = ra[0], mx = rb[0];
        int bin = bin255(val, mn, mx);
        g_pabin[b * 256 + t] = bin;
        atomicAdd(&hist[bin], 1);
        __syncthreads();
        g_histpa[b * 256 + t] = hist[t];
        const int4* h4 = (const int4*)hist;
        for (int u = t; u <= 256; u += 256) {
            float acc = 0.0f;
#pragma unroll 8
            for (int j4 = 0; j4 < 64; j4++) {
                int4 hh = h4[j4];
                acc += gts[512 - u - hh.x] + gts[512 - u - hh.y] + gts[512 - u - hh.z] + gts[512 - u - hh.w];
            }
            g_rowsum[b * 257 + u] = acc;
        }
    } else if (blk < 520) {
        GRID_DEP_SYNC();           // g_fmn/g_fmx/g_fpm ready (mid)
        int hb = blk - 8;
        int b = hb >> 6, chunk = hb & 63;
        __shared__ float ra[64], rb[64];
        __shared__ __align__(16) int hist[256];
        __shared__ int amlast;
        __shared__ float wr[8];
        if (t < 64) { ra[t] = g_fmn[b * 64 + t]; rb[t] = g_fmx[b * 64 + t]; }
        hist[t] = 0;
        __syncthreads();
        if (t < 32) {
            float mn = fminf(ra[t], ra[t + 32]);
            float mx = fmaxf(rb[t], rb[t + 32]);
#pragma unroll
            for (int o = 16; o > 0; o >>= 1) {
                mn = fminf(mn, __shfl_xor_sync(0xffffffffu, mn, o));
                mx = fmaxf(mx, __shfl_xor_sync(0xffffffffu, mx, o));
            }
            if (t == 0) { ra[0] = mn; rb[0] = mx; }
        }
        __syncthreads();
        float mn = ra[0], mx = rb[0];
        const float* base = g_fpm + b * HW + chunk * 1024;
#pragma unroll
        for (int i = 0; i < 4; i++) {
            float v = base[i * 256 + t];
            atomicAdd(&hist[bin255(v, mn, mx)], 1);
        }
        __syncthreads();
        if (hist[t] > 0) atomicAdd(&g_histB[b * 256 + t], hist[t]);
        __threadfence();
        if (t == 0) amlast = (atomicAdd(&g_cnt_hist, 1) == 511);
        __syncthreads();
        if (amlast) {
            // last histB block computes hp for all 8 batches (deterministic)
            for (int bb = 0; bb < 8; bb++) {
                float p = (float)g_histB[bb * 256 + t] * (1.0f / 65536.0f);
                float e = wredsum(-p * logf(p + 1e-8f));
                if ((t & 31) == 0) wr[t >> 5] = e;
                __syncthreads();
                if (t == 0) {
                    float s = 0.0f;
                    for (int q = 0; q < 8; q++) s += wr[q];
                    g_hp[bb] = s;
                }
                __syncthreads();
            }
        }
    } else {
        // ---- ms part (fms-only): fully overlapped with upstream ----
        int bc = blk - 520;
        int b = bc >> 6;
        int lane = t & 31, wid = t >> 5;
        __shared__ float sv[256];
        __shared__ float Gsh[256], Nsh[256];
        __shared__ __align__(16) int hist[256];
        __shared__ float val[64];
        __shared__ float wr1[8], wr2[8];
        __shared__ float s_mn, s_mx, s_meana, s_na;
        float v = fms[bc * 256 + t];
        sv[t] = v;
        hist[t] = 0;
        {
            int i = t >> 4, j = t & 15;
            float g = 0.0f;
            int d = i - j; if (d < 0) d = -d;
            if (d <= 1) {
                int mnij = i < j ? i : j, mxij = i < j ? j : i;
                int lo = 16 * mnij - 8; if (lo < 0) lo = 0;
                int hi = 16 * mxij + 24; if (hi > 256) hi = 256;
                for (int o = lo; o < hi; o++) g += up_w(o, i) * up_w(o, j);
            }
            Gsh[t] = g;
        }
        float mn = v, mx = v;
#pragma unroll
        for (int o = 16; o > 0; o >>= 1) {
            mn = fminf(mn, __shfl_xor_sync(0xffffffffu, mn, o));
            mx = fmaxf(mx, __shfl_xor_sync(0xffffffffu, mx, o));
        }
        if (lane == 0) { wr1[wid] = mn; wr2[wid] = mx; }
        __syncthreads();
        if (t == 0) {
            for (int q = 1; q < 8; q++) { wr1[0] = fminf(wr1[0], wr1[q]); wr2[0] = fmaxf(wr2[0], wr2[q]); }
            s_mn = wr1[0]; s_mx = wr2[0];
        }
        __syncthreads();
        int bin = bin255(v, s_mn, s_mx);
        g_msbin[bc * 256 + t] = bin;
        atomicAdd(&hist[bin], 1);
        __syncthreads();
        int h = hist[t];
        g_histms[bc * 256 + t] = h;
        float p = h * (1.0f / 256.0f);
        float ent = wredsum(-p * logf(p + 1e-8f));
        if (lane == 0) wr1[wid] = ent;
        {
            int i = t >> 4, j = t & 15;
            float n = 0.0f;
#pragma unroll
            for (int k = 0; k < 16; k++) n += sv[i * 16 + k] * Gsh[k * 16 + j];
            Nsh[t] = n;
        }
        __syncthreads();
        if (t == 0) {
            float s = 0.0f;
            for (int q = 0; q < 8; q++) s += wr1[q];
            g_hms[bc] = s;
        }
        float pp = 0.0f;
        {
            int i = t >> 4, j = t & 15;
#pragma unroll
            for (int k = 0; k < 16; k++) pp += Nsh[i * 16 + k] * sv[j * 16 + k];
        }
        float t1 = wredsum(Gsh[t] * pp);
        float t2 = wredsum(v);
        __syncthreads();
        if (lane == 0) { wr1[wid] = t1; wr2[wid] = t2; }
        __syncthreads();
        if (t == 0) {
            float SU2 = 0.0f, SM = 0.0f;
            for (int q = 0; q < 8; q++) { SU2 += wr1[q]; SM += wr2[q]; }
            float SU = 256.0f * SM;
            s_meana = SU * (1.0f / 65536.0f);
            s_na = __fsqrt_rn(SU2 - SU * SU * (1.0f / 65536.0f));
            g_meana[bc] = s_meana;
            g_na[bc] = s_na;
        }
        __syncthreads();
        GRID_DEP_SYNC();           // g_ap/g_sum/g_sumsq from mid
        float meana = s_meana;
#pragma unroll
        for (int rr = 0; rr < 8; rr++) {
            int row = wid * 8 + rr;
            const float* ap = g_ap + (size_t)(b * 64 + row) * 256;
            float d = 0.0f;
#pragma unroll
            for (int q = 0; q < 8; q++) d += sv[lane + 32 * q] * ap[lane + 32 * q];
            d = wredsum(d);
            if (lane == 0) val[row] = d - meana * g_sum[b * 64 + row];
        }
        __syncthreads();
        if (t == 0) {
            float mxv = val[0]; int am = 0;
            for (int d = 1; d < 64; d++) if (val[d] > mxv) { mxv = val[d]; am = d; }
            float nb = __fsqrt_rn(g_sumsq[bc] - g_sum[bc] * g_sum[bc] * (1.0f / 65536.0f));
            float den = __fmul_rn(s_na * nb, 0.01f);
            g_mxv[bc] = __fdiv_rn(mxv, den);
            g_amx[bc] = am;
        }
    }
}

// ========== K4: final w/ local grpsel (0..511) + joint (512..1023) ==========
__global__ void joint_final_kernel(const float* __restrict__ fp, float* __restrict__ out) {
    int t = threadIdx.x;
    if (blockIdx.x < 512) {
        int blk = blockIdx.x;
        int b = blk >> 6;
        int p4 = ((blk & 63) << 8) | t;
        __shared__ float sc[64], gsh[64], sortedv[64], wsh[64];
        __shared__ int ordsh[64], uniqcnt[8];
        __shared__ int mksh;
        GRID_DEP_SYNC();           // g_mxv/g_amx from L3
        if (t < 8) uniqcnt[t] = 0;
        if (t < 64) sc[t] = g_mxv[b * 64 + t];
        __syncthreads();
        if (t == 0) {
            float mx = sc[0];
            for (int c = 1; c < 64; c++) mx = fmaxf(mx, sc[c]);
            float s = 0.0f;
            for (int c = 0; c < 64; c++) { sc[c] = expf(sc[c] - mx); s += sc[c]; }
            float inv = 1.0f / s;
            for (int c = 0; c < 64; c++) sc[c] *= inv;
        }
        __syncthreads();
        if (t < 64) {
            float g = 0.0f;
            for (int j = 0; j < 64; j++) if (g_amx[b * 64 + j] == t) g += sc[j];
            gsh[t] = g;
        }
#pragma unroll
        for (int k = 0; k < 2; k++) {
            int task = t + 256 * k;            // 0..511 = (bb, group)
            int bb = task >> 6, ii = task & 63;
            int present = 0;
            for (int j = 0; j < 64; j++) present |= (g_amx[bb * 64 + j] == ii) ? 1 : 0;
            if (present) atomicAdd(&uniqcnt[bb], 1);
        }
        __syncthreads();
        if (t == 0) {
            int m = uniqcnt[0];
            for (int q = 1; q < 8; q++) m = min(m, uniqcnt[q]);
            mksh = (m + 1) >> 1;
        }
        __syncthreads();
        if (t < 64) {
            float vi = gsh[t];
            int r = 0;
            for (int j = 0; j < 64; j++) {
                float vj = gsh[j];
                if (vj > vi || (vj == vi && j < t)) r++;
            }
            ordsh[r] = t; sortedv[r] = vi;
        }
        __syncthreads();
        if (t == 0) {
            int m = mksh;
            float mx = sortedv[0];
            float s = 0.0f;
            for (int q = 0; q < m; q++) { float e = expf(sortedv[q] - mx); sortedv[q] = e; s += e; }
            float inv = 1.0f / s;
            for (int q = 0; q < m; q++) wsh[q] = sortedv[q] * inv;
            for (int q = m; q < 64; q++) wsh[q] = 0.0f;
        }
        __syncthreads();
        const float4* base = (const float4*)fp + (size_t)b * C_ * 16384;
        float4 m = make_float4(0.f, 0.f, 0.f, 0.f);
        int mk4 = (mksh + 3) & ~3;
        for (int r = 0; r < mk4; r += 4) {
            float4 v0 = base[(size_t)ordsh[r]     * 16384 + p4];
            float4 v1 = base[(size_t)ordsh[r + 1] * 16384 + p4];
            float4 v2 = base[(size_t)ordsh[r + 2] * 16384 + p4];
            float4 v3 = base[(size_t)ordsh[r + 3] * 16384 + p4];
            float w0 = wsh[r], w1 = wsh[r + 1], w2 = wsh[r + 2], w3 = wsh[r + 3];
            m.x += w0 / (1.0f + expf(-v0.x));
            m.y += w0 / (1.0f + expf(-v0.y));
            m.z += w0 / (1.0f + expf(-v0.z));
            m.w += w0 / (1.0f + expf(-v0.w));
            m.x += w1 / (1.0f + expf(-v1.x));
            m.y += w1 / (1.0f + expf(-v1.y));
            m.z += w1 / (1.0f + expf(-v1.z));
            m.w += w1 / (1.0f + expf(-v1.w));
            m.x += w2 / (1.0f + expf(-v2.x));
            m.y += w2 / (1.0f + expf(-v2.y));
            m.z += w2 / (1.0f + expf(-v2.z));
            m.w += w2 / (1.0f + expf(-v2.w));
            m.x += w3 / (1.0f + expf(-v3.x));
            m.y += w3 / (1.0f + expf(-v3.y));
            m.z += w3 / (1.0f + expf(-v3.z));
            m.w += w3 / (1.0f + expf(-v3.w));
        }
        float4 scl = make_float4(1.0f + m.x, 1.0f + m.y, 1.0f + m.z, 1.0f + m.w);
        float4* ob = (float4*)out + (size_t)b * C_ * 16384;
#pragma unroll 8
        for (int c = 0; c < 64; c++) {
            float4 v = base[(size_t)c * 16384 + p4];
            v.x *= scl.x; v.y *= scl.y; v.z *= scl.z; v.w *= scl.w;
            ob[(size_t)c * 16384 + p4] = v;
        }
    } else {
        int bc = blockIdx.x - 512;
        int b = bc >> 6;
        int lane = t & 31, wid = t >> 5;
        __shared__ __align__(16) int keys[256];
        __shared__ float gts[513];
        __shared__ float wr[8];
        for (int e = t; e < 513; e += 256) gts[e] = gfun((float)(e - 256));
        GRID_DEP_SYNC();
        int u = g_msbin[bc * 256 + t];
        int v = g_pabin[b * 256 + t];
        keys[t] = u * 256 + v;
        __syncthreads();
        float acc = g_rowsum[b * 257 + g_histms[bc * 256 + t]];
        int my = keys[t], J = 0; bool first = true;
        const int4* k4 = (const int4*)keys;
#pragma unroll 4
        for (int q4 = 0; q4 < 64; q4++) {
            int4 kk = k4[q4];
            int qb = q4 << 2;
            if (kk.x == my) { J++; if (qb < t) first = false; }
            if (kk.y == my) { J++; if (qb + 1 < t) first = false; }
            if (kk.z == my) { J++; if (qb + 2 < t) first = false; }
            if (kk.w == my) { J++; if (qb + 3 < t) first = false; }
        }
        if (first) {
            int hm = g_histms[bc * 256 + u];
            int hp = g_histpa[b * 256 + v];
            int cold = 256 - hm - hp;
            acc += gts[cold + 2 * J + 256] - gts[cold + 256];
        }
        acc = wredsum(acc);
        if (lane == 0) wr[wid] = acc;
        __syncthreads();
        if (t == 0) {
            float s = 0.0f;
            for (int q = 0; q < 8; q++) s += wr[q];
            g_mi[bc] = g_hp[b] + g_hms[bc] - s;
        }
    }
}

// ========== K5: softmax(mi) + rel_ms output ==========
__global__ void relms_kernel(const float* __restrict__ fms, float* __restrict__ out) {
    GRID_DEP_SYNC();
    int b = blockIdx.x, t = threadIdx.x;
    __shared__ float mi[64];
    if (t < 64) mi[t] = g_mi[b * 64 + t];
    __syncthreads();
    if (t == 0) {
        float mx = mi[0];
        for (int c = 1; c < 64; c++) mx = fmaxf(mx, mi[c]);
        float s = 0.0f;
        for (int c = 0; c < 64; c++) { mi[c] = expf(mi[c] - mx); s += mi[c]; }
        float inv = 1.0f / s;
        for (int c = 0; c < 64; c++) mi[c] *= inv;
    }
    __syncthreads();
    for (int c = 0; c < 64; c++) {
        int idx = (b * 64 + c) * 256 + t;
        float vv = fms[idx];
        out[RELP + idx] = vv + vv * mi[c];
    }
}

// ---------------- host: PDL launches with plain fallback ----------------
template <typename K, typename... Args>
static inline void launch_pdl(K kernel, dim3 grid, dim3 block, bool pdl, Args... args) {
    cudaLaunchConfig_t cfg = {};
    cfg.gridDim = grid;
    cfg.blockDim = block;
    cfg.dynamicSmemBytes = 0;
    cfg.stream = 0;
    cudaLaunchAttribute attr[1];
    if (pdl) {
        attr[0].id = cudaLaunchAttributeProgrammaticStreamSerialization;
        attr[0].val.programmaticStreamSerializationAllowed = 1;
        cfg.attrs = attr;
        cfg.numAttrs = 1;
    }
    cudaError_t err = cudaLaunchKernelEx(&cfg, kernel, args...);
    if (err != cudaSuccess) {
        (void)cudaGetLastError();
        cfg.attrs = nullptr; cfg.numAttrs = 0;
        cudaLaunchKernelEx(&cfg, kernel, args...);
    }
}

extern "C" void kernel_launch(void* const* d_in, const int* in_sizes, int n_in,
                              void* d_out, int out_size) {
    const float* fp  = (const float*)d_in[0];
    const float* fms = (const float*)d_in[1];
    if (n_in >= 2 && in_sizes[0] == B_ * C_ * 256) {
        fp  = (const float*)d_in[1];
        fms = (const float*)d_in[0];
    }
    float* out = (float*)d_out;

    launch_pdl(bigpass_kernel,        dim3(512),  dim3(256), false, fp);
    launch_pdl(mid_kernel,            dim3(1024), dim3(256), true);
    launch_pdl(pa_hist_mssmat_kernel, dim3(1032), dim3(256), true,  fms);
    launch_pdl(joint_final_kernel,    dim3(1024), dim3(256), true,  fp, out);
    launch_pdl(relms_kernel,          dim3(B_),   dim3(256), true,  fms, out);
}